// round 11
// baseline (speedup 1.0000x reference)
#include <cuda_runtime.h>
#include <cuda_fp16.h>
#include <math.h>

#define BB 128       // batch
#define T_ENC 2048
#define T_DEC 256
#define HID 256
#define KEY 128
#define VAL 128
#define H1S 512      // lstm1 hidden
#define VOCAB 1000
#define NBLK 296     // 2 CTAs/SM * 148 SMs, all resident
#define NTHR 256
#define NROWS (T_DEC*BB)   // 32768

// ---------------- device scratch (static) ----------------
__device__ unsigned g_leaf[8*64];    // gbar-all leaves (256B apart)
__device__ unsigned g_root;
__device__ unsigned g_leafB[4*64];   // barB leaves (blocks 0-127)
__device__ unsigned g_rootB;
__device__ int g_jobc[256];          // per-phase A' job queue counters
__device__ float g_embT[(size_t)T_DEC*HID*BB];          // [t][h][b]
__device__ float g_h2ctxT[(size_t)(KEY+VAL)*NROWS];     // [f][t*BB+b]
__device__ float g_h1T[H1S*BB];                         // [j][b]
__device__ float g_c1T[H1S*BB];
__device__ float g_h2T[2][KEY*BB];
__device__ float g_c2T[KEY*BB];
__device__ float g_ctxT[VAL*BB];                        // [v][b]
__device__ float g_g1p[(size_t)2*2*128*16*64];          // [ks][b0sel][n][ci][r]
__device__ float g_W1p[(size_t)128*896*16];             // [tile][k][16]
__device__ float g_W2p[(size_t)32*640*16];
__device__ __align__(16) __half g_khT[(size_t)BB*KEY*T_ENC];  // [b][k][t]
__device__ __align__(16) __half g_vh[(size_t)T_ENC*BB*VAL];   // [t][b][v]

// ---------------- barriers (monotonic, hierarchical) ----------------
__device__ __forceinline__ void gbar(int bid, unsigned ph) {
    __syncthreads();
    if (threadIdx.x == 0) {
        __threadfence();
        int g = bid & 7;                       // 37 blocks per leaf
        unsigned old = atomicAdd(&g_leaf[g*64], 1u);
        if (old == ph*37u - 1u) atomicAdd(&g_root, 1u);
        while (*(volatile unsigned*)&g_root < ph*8u) __nanosleep(32);
        __threadfence();
    }
    __syncthreads();
}
// barrier among blocks 0..127 only
__device__ __forceinline__ void barB(int bid, unsigned ph) {
    __syncthreads();
    if (threadIdx.x == 0) {
        __threadfence();
        int g = bid & 3;                       // 32 blocks per leaf
        unsigned old = atomicAdd(&g_leafB[g*64], 1u);
        if (old == ph*32u - 1u) atomicAdd(&g_rootB, 1u);
        while (*(volatile unsigned*)&g_rootB < ph*4u) __nanosleep(32);
        __threadfence();
    }
    __syncthreads();
}

__global__ void reset_bar_kernel() {
    int i = threadIdx.x;
    if (i < 8*64) g_leaf[i] = 0u;
    if (i < 4*64) g_leafB[i] = 0u;
    if (i < 256) g_jobc[i] = 0;
    if (i == 0) { g_root = 0u; g_rootB = 0u; }
}

__device__ __forceinline__ float sigf(float x) { return 1.f / (1.f + expf(-x)); }

// pull next A' job id from phase queue; block-uniform result via smem
__device__ __forceinline__ int pull_job(int phase, float* sm, int tid, int base) {
    int* slot = (int*)(sm + 4100);
    __syncthreads();
    if (tid == 0) *slot = base + atomicAdd(&g_jobc[phase], 1);
    __syncthreads();
    return *slot;
}

// ---------------- A': emb+h1 partial GEMM, half-K job -----------------
// J in [0,512): ks=J>>8 (K-half of 384), b0sel=(J>>7)&1, n=J&127
// Output: g_g1p[ks][b0sel][n][16 ci][64 r]
__device__ __forceinline__ void aprime_job(int J, int tnext, float* sm, int tid) {
    const int ks = J >> 8;
    const int rj = J & 255;
    const int b0 = (rj >> 7) * 64;
    const int n  = rj & 127;
    const int kb = ks * 384;            // base in local 768-space (emb|h1)
    const int q  = tid >> 6;            // quadrant: 96 k each
    const int qt = tid & 63;
    const int r4 = (qt & 15) * 4;
    const int c4 = (qt >> 4) * 4;
    const float* Wp = g_W1p + (size_t)n * (896*16);
    float acc[4][4];
    #pragma unroll
    for (int i = 0; i < 4; i++)
        #pragma unroll
        for (int jj = 0; jj < 4; jj++) acc[i][jj] = 0.f;

    float* As = sm;           // [4][8][64]
    float* Bs = sm + 2048;    // [4][8][16]
    float ra[8], rb[2];

    // prefetch iter 0
    #pragma unroll
    for (int i = 0; i < 8; i++) {
        int li = i*256 + tid;
        int kl = kb + (li >> 9)*96 + ((li >> 6) & 7);
        int b = b0 + (li & 63);
        ra[i] = (kl < HID) ? g_embT[((size_t)tnext*HID + kl)*BB + b]
                           : g_h1T[(kl - HID)*BB + b];
    }
    #pragma unroll
    for (int i = 0; i < 2; i++) {
        int li = i*256 + tid;
        int kl = kb + (li >> 7)*96 + ((li >> 4) & 7);
        int kg = (kl < HID) ? kl : kl + VAL;   // skip ctx cols in packed W
        rb[i] = Wp[kg*16 + (li & 15)];
    }

    for (int it = 0; it < 12; it++) {
        #pragma unroll
        for (int i = 0; i < 8; i++) {
            int li = i*256 + tid;
            As[(li >> 9)*512 + ((li >> 6) & 7)*64 + (li & 63)] = ra[i];
        }
        #pragma unroll
        for (int i = 0; i < 2; i++) {
            int li = i*256 + tid;
            Bs[(li >> 7)*128 + ((li >> 4) & 7)*16 + (li & 15)] = rb[i];
        }
        __syncthreads();
        if (it < 11) {
            #pragma unroll
            for (int i = 0; i < 8; i++) {
                int li = i*256 + tid;
                int kl = kb + (li >> 9)*96 + (it+1)*8 + ((li >> 6) & 7);
                int b = b0 + (li & 63);
                ra[i] = (kl < HID) ? g_embT[((size_t)tnext*HID + kl)*BB + b]
                                   : g_h1T[(kl - HID)*BB + b];
            }
            #pragma unroll
            for (int i = 0; i < 2; i++) {
                int li = i*256 + tid;
                int kl = kb + (li >> 7)*96 + (it+1)*8 + ((li >> 4) & 7);
                int kg = (kl < HID) ? kl : kl + VAL;
                rb[i] = Wp[kg*16 + (li & 15)];
            }
        }
        #pragma unroll
        for (int kk = 0; kk < 8; kk++) {
            float4 a  = *(float4*)&As[q*512 + kk*64 + r4];
            float4 bq = *(float4*)&Bs[q*128 + kk*16 + c4];
            float av[4] = {a.x, a.y, a.z, a.w};
            float bv[4] = {bq.x, bq.y, bq.z, bq.w};
            #pragma unroll
            for (int i = 0; i < 4; i++)
                #pragma unroll
                for (int jj = 0; jj < 4; jj++)
                    acc[i][jj] += av[i] * bv[jj];
        }
        __syncthreads();
    }
    float* red = sm;  // [4][1024]
    #pragma unroll
    for (int i = 0; i < 4; i++)
        *(float4*)&red[q*1024 + (r4+i)*16 + c4] =
            make_float4(acc[i][0], acc[i][1], acc[i][2], acc[i][3]);
    __syncthreads();
    {   // write partial (coalesced over r)
        int r = tid & 63, cb = tid >> 6;
        float* dst = g_g1p + (((size_t)ks*2 + (rj >> 7))*128 + n)*1024;
        #pragma unroll
        for (int i = 0; i < 4; i++) {
            int ci = cb*4 + i;
            float s = 0.f;
            #pragma unroll
            for (int qq = 0; qq < 4; qq++)
                s += red[qq*1024 + r*16 + ci];
            dst[ci*64 + r] = s;
        }
    }
    __syncthreads();   // protect red (==As) before next job
}

// =============================================================================
// Persistent decoder kernel
// =============================================================================
__global__ __launch_bounds__(NTHR, 2) void decoder_kernel(
    const float* __restrict__ keys, const float* __restrict__ values,
    const int* __restrict__ lens, const int* __restrict__ text,
    const float* __restrict__ emb_table,
    const float* __restrict__ Wih1, const float* __restrict__ Whh1,
    const float* __restrict__ bih1, const float* __restrict__ bhh1,
    const float* __restrict__ Wih2, const float* __restrict__ Whh2,
    const float* __restrict__ bih2, const float* __restrict__ bhh2)
{
    __shared__ float sm[4160];
    const int tid = threadIdx.x;
    const int bid = blockIdx.x;
    const int gid = bid * NTHR + tid;
    const int gstride = NBLK * NTHR;   // 75776
    unsigned nb = 0, nbB = 0;

    // ---------------- pre-stage ----------------
    for (int i = gid; i < H1S*BB;   i += gstride) { g_h1T[i] = 0.f; g_c1T[i] = 0.f; }
    for (int i = gid; i < 2*KEY*BB; i += gstride) ((float*)g_h2T)[i] = 0.f;
    for (int i = gid; i < KEY*BB;   i += gstride) g_c2T[i] = 0.f;
    for (int i = gid; i < VAL*BB;   i += gstride) g_ctxT[i] = 0.f;

    // embedding gather -> [t][h][b]
    for (int i = gid; i < T_DEC*HID*BB; i += gstride) {
        int b = i & (BB-1);
        int f = i >> 7;
        int h = f & (HID-1);
        int t = f >> 8;
        g_embT[i] = emb_table[text[b*T_DEC + t]*HID + h];
    }

    // pack W1 -> [128 tiles][896 k][16 cols] (gate-grouped: ci = gate*4 + jj)
    for (int i = gid; i < 128*896*16; i += gstride) {
        int ci = i & 15;
        int k  = (i >> 4) % 896;
        int n  = i / (896*16);
        int c  = n*4 + (ci & 3) + H1S * (ci >> 2);
        g_W1p[i] = (k < HID+VAL) ? Wih1[c*(HID+VAL) + k]
                                 : Whh1[c*H1S + (k - HID - VAL)];
    }
    // pack W2 -> [32 tiles][640 k][16 cols]
    for (int i = gid; i < 32*640*16; i += gstride) {
        int ci = i & 15;
        int k  = (i >> 4) % 640;
        int n  = i / (640*16);
        int c  = n*4 + (ci & 3) + KEY * (ci >> 2);
        g_W2p[i] = (k < H1S) ? Wih2[c*H1S + k] : Whh2[c*KEY + (k - H1S)];
    }

    // convert V to fp16 ([t][b][v] layout kept)
    {
        const int n4 = (T_ENC*BB*VAL) / 4;
        const float4* v4 = (const float4*)values;
        __half2* vh2 = (__half2*)g_vh;
        for (int i = gid; i < n4; i += gstride) {
            float4 f = v4[i];
            vh2[2*i]   = __floats2half2_rn(f.x, f.y);
            vh2[2*i+1] = __floats2half2_rn(f.z, f.w);
        }
    }

    // transpose K -> fp16 [b][k][t] via smem tiles (64 t x 32 k per job)
    for (int j = bid; j < 128*4*32; j += NBLK) {
        int b  = j >> 7;
        int kt = (j >> 5) & 3;
        int tt = j & 31;
        float* st = sm;           // [64][33]
        #pragma unroll
        for (int p8 = 0; p8 < 8; p8++) {
            int trow = p8*8 + (tid >> 5);
            int kcol = tid & 31;
            st[trow*33 + kcol] =
                keys[((size_t)(tt*64 + trow)*BB + b)*KEY + kt*32 + kcol];
        }
        __syncthreads();
        #pragma unroll
        for (int p4 = 0; p4 < 8; p4++) {
            int kr   = p4*4 + (tid >> 6);
            int tcol = tid & 63;
            g_khT[((size_t)b*KEY + kt*32 + kr)*T_ENC + tt*64 + tcol] =
                __float2half_rn(st[tcol*33 + kr]);
        }
        __syncthreads();
    }
    nb++; gbar(bid, nb);

    // ---------------- A'_0: partial gates for t=0 (static + queue) ---------
    {
        int J = bid;                              // 296 static jobs
        while (J < 512) {
            aprime_job(J, 0, sm, tid);
            J = pull_job(0, sm, tid, 296);
        }
    }
    nb++; gbar(bid, nb);

    // ================= decode loop =================
    for (int t = 0; t < T_DEC; t++) {
        const int p = t & 1, pn = p ^ 1;

        // ---------- Interval 1: A'' = ctx-part GEMM (K=128) + cell1 ----------
        if (bid < 256) {
            const int b0 = (bid >> 7) * 64;
            const int n  = bid & 127;
            const int j0 = n * 4;
            const int q  = tid >> 6;          // 32 k per quadrant
            const int qt = tid & 63;
            const int r4 = (qt & 15) * 4;
            const int c4 = (qt >> 4) * 4;
            const float* Wp = g_W1p + (size_t)n * (896*16);
            float acc[4][4];
            #pragma unroll
            for (int i = 0; i < 4; i++)
                #pragma unroll
                for (int jj = 0; jj < 4; jj++) acc[i][jj] = 0.f;

            float* As = sm;           // [4][8][64]
            float* Bs = sm + 2048;    // [4][8][16]

            for (int it = 0; it < 4; it++) {
                #pragma unroll
                for (int i = 0; i < 8; i++) {
                    int li = i*256 + tid;
                    int k = (li >> 9)*32 + it*8 + ((li >> 6) & 7);
                    As[(li >> 9)*512 + ((li >> 6) & 7)*64 + (li & 63)] =
                        g_ctxT[k*BB + b0 + (li & 63)];
                }
                #pragma unroll
                for (int i = 0; i < 2; i++) {
                    int li = i*256 + tid;
                    int k = (li >> 7)*32 + it*8 + ((li >> 4) & 7);
                    Bs[(li >> 7)*128 + ((li >> 4) & 7)*16 + (li & 15)] =
                        Wp[(HID + k)*16 + (li & 15)];
                }
                __syncthreads();
                #pragma unroll
                for (int kk = 0; kk < 8; kk++) {
                    float4 a  = *(float4*)&As[q*512 + kk*64 + r4];
                    float4 bq = *(float4*)&Bs[q*128 + kk*16 + c4];
                    float av[4] = {a.x, a.y, a.z, a.w};
                    float bv[4] = {bq.x, bq.y, bq.z, bq.w};
                    #pragma unroll
                    for (int i = 0; i < 4; i++)
                        #pragma unroll
                        for (int jj = 0; jj < 4; jj++)
                            acc[i][jj] += av[i] * bv[jj];
                }
                __syncthreads();
            }
            float* red = sm;  // [4][1024]
            #pragma unroll
            for (int i = 0; i < 4; i++)
                *(float4*)&red[q*1024 + (r4+i)*16 + c4] =
                    make_float4(acc[i][0], acc[i][1], acc[i][2], acc[i][3]);
            __syncthreads();
            {   // epilogue: both K-half partials + ctx-part + bias -> cell1
                int r = tid & 63, jj = tid >> 6;
                const float* par0 = g_g1p + ((size_t)(bid >> 7)*128 + n)*1024;
                const float* par1 = g_g1p + ((size_t)(2 + (bid >> 7))*128 + n)*1024;
                float gsum[4];
                #pragma unroll
                for (int g = 0; g < 4; g++) {
                    int ci = jj + 4*g;
                    float s = par0[ci*64 + r] + par1[ci*64 + r];
                    #pragma unroll
                    for (int qq = 0; qq < 4; qq++)
                        s += red[qq*1024 + r*16 + ci];
                    gsum[g] = s;
                }
                int b = b0 + r, j = j0 + jj;
                float gi = gsum[0] + bih1[j]         + bhh1[j];
                float gf = gsum[1] + bih1[j +   H1S] + bhh1[j +   H1S];
                float gg = gsum[2] + bih1[j + 2*H1S] + bhh1[j + 2*H1S];
                float go = gsum[3] + bih1[j + 3*H1S] + bhh1[j + 3*H1S];
                int idx = j*BB + b;
                float c = sigf(gf) * g_c1T[idx] + sigf(gi) * tanhf(gg);
                g_c1T[idx] = c;
                g_h1T[idx] = sigf(go) * tanhf(c);
            }
        }
        nb++; gbar(bid, nb);

        // ---------- Interval 2: {B -> barB -> C -> join A'} || A'_{t+1} -----
        if (bid < 128) {
            // ----- Stage B: gemm2 + cell2 -----
            const int b0 = (bid >> 5) * 32;
            const int n  = bid & 31;
            const int j0 = n * 4;
            const int q  = tid >> 6;          // 160 k per quadrant
            const int qt = tid & 63;
            const int r2 = (qt & 15) * 2;
            const int c4 = (qt >> 4) * 4;
            const float* Wp = g_W2p + (size_t)n * (640*16);
            float acc[2][4];
            #pragma unroll
            for (int i = 0; i < 2; i++)
                #pragma unroll
                for (int jj = 0; jj < 4; jj++) acc[i][jj] = 0.f;

            float* As = sm;           // [4][8][32]
            float* Bs = sm + 1024;    // [4][8][16]
            float ra[4], rb[2];

            #pragma unroll
            for (int i = 0; i < 4; i++) {
                int li = i*256 + tid;
                int k = (li >> 8)*160 + ((li >> 5) & 7);
                int b = b0 + (li & 31);
                ra[i] = (k < H1S) ? g_h1T[k*BB + b]
                                  : g_h2T[p][(k - H1S)*BB + b];
            }
            #pragma unroll
            for (int i = 0; i < 2; i++) {
                int li = i*256 + tid;
                int k = (li >> 7)*160 + ((li >> 4) & 7);
                rb[i] = Wp[k*16 + (li & 15)];
            }

            for (int it = 0; it < 20; it++) {
                #pragma unroll
                for (int i = 0; i < 4; i++) {
                    int li = i*256 + tid;
                    As[(li >> 8)*256 + ((li >> 5) & 7)*32 + (li & 31)] = ra[i];
                }
                #pragma unroll
                for (int i = 0; i < 2; i++) {
                    int li = i*256 + tid;
                    Bs[(li >> 7)*128 + ((li >> 4) & 7)*16 + (li & 15)] = rb[i];
                }
                __syncthreads();
                if (it < 19) {
                    #pragma unroll
                    for (int i = 0; i < 4; i++) {
                        int li = i*256 + tid;
                        int k = (li >> 8)*160 + (it+1)*8 + ((li >> 5) & 7);
                        int b = b0 + (li & 31);
                        ra[i] = (k < H1S) ? g_h1T[k*BB + b]
                                          : g_h2T[p][(k - H1S)*BB + b];
                    }
                    #pragma unroll
                    for (int i = 0; i < 2; i++) {
                        int li = i*256 + tid;
                        int k = (li >> 7)*160 + (it+1)*8 + ((li >> 4) & 7);
                        rb[i] = Wp[k*16 + (li & 15)];
                    }
                }
                #pragma unroll
                for (int kk = 0; kk < 8; kk++) {
                    float2 a  = *(float2*)&As[q*256 + kk*32 + r2];
                    float4 bq = *(float4*)&Bs[q*128 + kk*16 + c4];
                    float av[2] = {a.x, a.y};
                    float bv[4] = {bq.x, bq.y, bq.z, bq.w};
                    #pragma unroll
                    for (int i = 0; i < 2; i++)
                        #pragma unroll
                        for (int jj = 0; jj < 4; jj++)
                            acc[i][jj] += av[i] * bv[jj];
                }
                __syncthreads();
            }
            float* red = sm;  // [4][512]
            #pragma unroll
            for (int i = 0; i < 2; i++)
                *(float4*)&red[q*512 + (r2+i)*16 + c4] =
                    make_float4(acc[i][0], acc[i][1], acc[i][2], acc[i][3]);
            __syncthreads();
            if (tid < 128) {   // 32 rows x 4 j
                int r = tid & 31, jj = tid >> 5;
                float gsum[4];
                #pragma unroll
                for (int g = 0; g < 4; g++) {
                    float s = 0.f;
                    #pragma unroll
                    for (int qq = 0; qq < 4; qq++)
                        s += red[qq*512 + r*16 + jj + 4*g];
                    gsum[g] = s;
                }
                int b = b0 + r, j = j0 + jj;
                float gi = gsum[0] + bih2[j]         + bhh2[j];
                float gf = gsum[1] + bih2[j +   KEY] + bhh2[j +   KEY];
                float gg = gsum[2] + bih2[j + 2*KEY] + bhh2[j + 2*KEY];
                float go = gsum[3] + bih2[j + 3*KEY] + bhh2[j + 3*KEY];
                int idx = j*BB + b;
                float c = sigf(gf) * g_c2T[idx] + sigf(gi) * tanhf(gg);
                g_c2T[idx] = c;
                float h = sigf(go) * tanhf(c);
                g_h2T[pn][idx] = h;
                g_h2ctxT[(size_t)j*NROWS + t*BB + b] = h;
            }
            nbB++; barB(bid, nbB);

            // ----- Stage C: attention, two-pass smem softmax -----
            {
                const int b = bid;
                const int lane = tid & 31, w = tid >> 5;
                const int len = lens[b];
                float* s_p  = sm;           // [2048]
                float* s_pt = sm + 2048;    // [8][128]
                float* s_h2 = sm + 3072;    // [128]
                float* s_r  = sm + 3200;    // [16]
                if (tid < 128) s_h2[tid] = g_h2T[pn][tid*BB + b];
                __syncthreads();

                const int t0 = tid * 8;
                float ef[8];
                #pragma unroll
                for (int i = 0; i < 8; i++) ef[i] = 0.f;
                if (t0 < len) {
                    const __half* kp = g_khT + (size_t)b*KEY*T_ENC + t0;
                    #pragma unroll 4
                    for (int k = 0; k < KEY; k++) {
                        uint4 u = *(const uint4*)(kp + (size_t)k*T_ENC);
                        float h = s_h2[k];
                        float2 f0 = __half22float2(((__half2*)&u)[0]);
                        float2 f1 = __half22float2(((__half2*)&u)[1]);
                        float2 f2 = __half22float2(((__half2*)&u)[2]);
                        float2 f3 = __half22float2(((__half2*)&u)[3]);
                        ef[0] += h*f0.x; ef[1] += h*f0.y;
                        ef[2] += h*f1.x; ef[3] += h*f1.y;
                        ef[4] += h*f2.x; ef[5] += h*f2.y;
                        ef[6] += h*f3.x; ef[7] += h*f3.y;
                    }
                }
                float e[8];
                #pragma unroll
                for (int i = 0; i < 8; i++)
                    e[i] = (t0 + i < len) ? ef[i] : -3.0e38f;

                float tm = e[0];
                #pragma unroll
                for (int i = 1; i < 8; i++) tm = fmaxf(tm, e[i]);
                #pragma unroll
                for (int off = 16; off; off >>= 1)
                    tm = fmaxf(tm, __shfl_xor_sync(~0u, tm, off));
                if (lane == 0) s_r[w] = tm;
                __syncthreads();
                float M = s_r[0];
                #pragma unroll
                for (int ww = 1; ww < 8; ww++) M = fmaxf(M, s_r[ww]);

                float pv[8];
                float lsum = 0.f;
                #pragma unroll
                for (int i = 0; i < 8; i++) {
                    pv[i] = expf(e[i] - M);
                    lsum += pv[i];
                }
                *(float4*)&s_p[t0]     = make_float4(pv[0], pv[1], pv[2], pv[3]);
                *(float4*)&s_p[t0 + 4] = make_float4(pv[4], pv[5], pv[6], pv[7]);
                #pragma unroll
                for (int off = 16; off; off >>= 1)
                    lsum += __shfl_xor_sync(~0u, lsum, off);
                if (lane == 0) s_r[8 + w] = lsum;
                __syncthreads();
                float L = 0.f;
                #pragma unroll
                for (int ww = 0; ww < 8; ww++) L += s_r[8 + ww];
                const float Linv = 1.f / L;

                const int vq = (tid & 31) * 4;
                const int tg = tid >> 5;
                float a0 = 0.f, a1 = 0.f, a2 = 0.f, a3 = 0.f;
                const int itmax = (len + 7) >> 3;
                for (int it = 0; it < itmax; it++) {
                    int tt = it*8 + tg;
                    float pw = s_p[tt];
                    uint2 u = *(const uint2*)(g_vh + ((size_t)tt*BB + b)*VAL + vq);
                    float2 f01 = __half22float2(((__half2*)&u)[0]);
                    float2 f23 = __half22float2(((__half2*)&u)[1]);
                    a0 += pw*f01.x; a1 += pw*f01.y;
                    a2 += pw*f23.x; a3 += pw*f23.y;
                }
                *(float4*)&s_pt[tg*128 + vq] = make_float4(a0, a1, a2, a3);
                __syncthreads();
                if (tid < 128) {
                    float s = 0.f;
                    #pragma unroll
                    for (int g8 = 0; g8 < 8; g8++) s += s_pt[g8*128 + tid];
                    float cx = s * Linv;
                    g_ctxT[tid*BB + b] = cx;
                    g_h2ctxT[(size_t)(KEY + tid)*NROWS + t*BB + b] = cx;
                }
            }
            // ----- join the A'_{t+1} queue after C -----
            if (t + 1 < T_DEC) {
                int J = pull_job(t + 1, sm, tid, 168);
                while (J < 512) {
                    aprime_job(J, t + 1, sm, tid);
                    J = pull_job(t + 1, sm, tid, 168);
                }
            }
        } else if (t + 1 < T_DEC) {
            // ----- A'_{t+1}: static first job + queue -----
            int J = bid - 128;                 // 0..167 static
            while (J < 512) {
                aprime_job(J, t + 1, sm, tid);
                J = pull_job(t + 1, sm, tid, 168);
            }
        }
        nb++; gbar(bid, nb);
    }
}

// ---------------- final logits GEMM -------------
__global__ __launch_bounds__(256) void pred_kernel(
    const float* __restrict__ Wlin, const float* __restrict__ blin,
    float* __restrict__ out)
{
    __shared__ float As[16][68];
    __shared__ float Bs[16][68];
    const int r0 = blockIdx.x * 64;
    const int v0 = blockIdx.y * 64;
    const int tid = threadIdx.x;
    const int m0 = (tid & 15) * 4;
    const int n0 = (tid >> 4) * 4;
    float acc[4][4] = {};

    for (int k0 = 0; k0 < 256; k0 += 16) {
        #pragma unroll
        for (int i = 0; i < 4; i++) {
            int li = i*256 + tid;
            int kk = li >> 6, m = li & 63;
            As[kk][m] = g_h2ctxT[(size_t)(k0 + kk)*NROWS + r0 + m];
        }
        #pragma unroll
        for (int i = 0; i < 4; i++) {
            int li = i*256 + tid;
            int n = li >> 4, kk = li & 15;
            int v = v0 + n;
            Bs[kk][n] = (v < VOCAB) ? Wlin[v*256 + k0 + kk] : 0.f;
        }
        __syncthreads();
        #pragma unroll
        for (int kk = 0; kk < 16; kk++) {
            float4 a = *(const float4*)&As[kk][m0];
            float4 bq = *(const float4*)&Bs[kk][n0];
            float av[4] = {a.x, a.y, a.z, a.w};
            float bv[4] = {bq.x, bq.y, bq.z, bq.w};
            #pragma unroll
            for (int i = 0; i < 4; i++)
                #pragma unroll
                for (int j = 0; j < 4; j++)
                    acc[i][j] += av[i] * bv[j];
        }
        __syncthreads();
    }
    #pragma unroll
    for (int i = 0; i < 4; i++) {
        int r = r0 + m0 + i;
        int b = r & 127, t = r >> 7;
        #pragma unroll
        for (int j = 0; j < 4; j++) {
            int v = v0 + n0 + j;
            if (v < VOCAB)
                out[((size_t)b*T_DEC + t)*VOCAB + v] = acc[i][j] + blin[v];
        }
    }
}

// ---------------- launch (decoder FIRST so ncu -s 5 lands on it) ---------
extern "C" void kernel_launch(void* const* d_in, const int* in_sizes, int n_in,
                              void* d_out, int out_size)
{
    const float* keys      = (const float*)d_in[0];
    const float* values    = (const float*)d_in[1];
    const int*   lens      = (const int*)  d_in[2];
    const int*   text      = (const int*)  d_in[3];
    const float* emb_table = (const float*)d_in[4];
    const float* Wih1      = (const float*)d_in[5];
    const float* Whh1      = (const float*)d_in[6];
    const float* bih1      = (const float*)d_in[7];
    const float* bhh1      = (const float*)d_in[8];
    const float* Wih2      = (const float*)d_in[9];
    const float* Whh2      = (const float*)d_in[10];
    const float* bih2      = (const float*)d_in[11];
    const float* bhh2      = (const float*)d_in[12];
    const float* Wlin      = (const float*)d_in[13];
    const float* blin      = (const float*)d_in[14];
    float* out = (float*)d_out;

    // Counters are statically zero-initialized; reset_bar_kernel at the END of
    // each launch restores that invariant for the next graph replay.
    decoder_kernel<<<NBLK, NTHR>>>(keys, values, lens, text, emb_table,
                                   Wih1, Whh1, bih1, bhh1,
                                   Wih2, Whh2, bih2, bhh2);
    pred_kernel<<<dim3(NROWS/64, (VOCAB + 63)/64), 256>>>(Wlin, blin, out);
    reset_bar_kernel<<<1, 512>>>();
}

// round 12
// speedup vs baseline: 1.0432x; 1.0432x over previous
#include <cuda_runtime.h>
#include <cuda_fp16.h>
#include <math.h>

#define BB 128       // batch
#define T_ENC 2048
#define T_DEC 256
#define HID 256
#define KEY 128
#define VAL 128
#define H1S 512      // lstm1 hidden
#define VOCAB 1000
#define NBLK 296     // 2 CTAs/SM * 148 SMs, all resident
#define NTHR 256
#define NROWS (T_DEC*BB)   // 32768
#define NKC 48       // k-chunks of 16 over K=768 (emb 256 | h1 512)

// ---------------- device scratch (static) ----------------
__device__ unsigned g_leaf[8*64];    // gbar-all leaves (256B apart)
__device__ unsigned g_root;
__device__ unsigned g_leafB[4*64];   // barB leaves (blocks 0-127)
__device__ unsigned g_rootB;
__device__ float g_h2ctxT[(size_t)(KEY+VAL)*NROWS];     // [f][t*BB+b]
__device__ float g_h1T[H1S*BB];                         // [j][b] fp32 (stage B)
__device__ float g_c1T[H1S*BB];
__device__ float g_h2T[2][KEY*BB];
__device__ float g_c2T[KEY*BB];
__device__ float g_ctxT[VAL*BB];                        // [v][b]
__device__ float g_g1p[(size_t)2*128*16*64];            // [b0sel][n][ci][r]
__device__ float g_W1p[(size_t)128*896*16];             // fp32 pack (A'' ctx part)
__device__ float g_W2p[(size_t)32*640*16];
__device__ __align__(16) __half g_W1h[(size_t)128*NKC*32*8]; // mma A-frag pack
__device__ __align__(16) __half g_embh[(size_t)T_DEC*BB*HID]; // [t][b][h] fp16
__device__ __align__(16) __half g_h1h[BB*H1S];               // [b][j] fp16
__device__ __align__(16) __half g_khT[(size_t)BB*KEY*T_ENC];  // [b][k][t]
__device__ __align__(16) __half g_vh[(size_t)T_ENC*BB*VAL];   // [t][b][v]

// ---------------- barriers (monotonic, hierarchical) ----------------
__device__ __forceinline__ void gbar(int bid, unsigned ph) {
    __syncthreads();
    if (threadIdx.x == 0) {
        __threadfence();
        int g = bid & 7;                       // 37 blocks per leaf
        unsigned old = atomicAdd(&g_leaf[g*64], 1u);
        if (old == ph*37u - 1u) atomicAdd(&g_root, 1u);
        while (*(volatile unsigned*)&g_root < ph*8u) __nanosleep(32);
        __threadfence();
    }
    __syncthreads();
}
// barrier among blocks 0..127 only
__device__ __forceinline__ void barB(int bid, unsigned ph) {
    __syncthreads();
    if (threadIdx.x == 0) {
        __threadfence();
        int g = bid & 3;                       // 32 blocks per leaf
        unsigned old = atomicAdd(&g_leafB[g*64], 1u);
        if (old == ph*32u - 1u) atomicAdd(&g_rootB, 1u);
        while (*(volatile unsigned*)&g_rootB < ph*4u) __nanosleep(32);
        __threadfence();
    }
    __syncthreads();
}

__global__ void reset_bar_kernel() {
    int i = threadIdx.x;
    if (i < 8*64) g_leaf[i] = 0u;
    if (i < 4*64) g_leafB[i] = 0u;
    if (i == 0) { g_root = 0u; g_rootB = 0u; }
}

__device__ __forceinline__ float sigf(float x) { return 1.f / (1.f + expf(-x)); }

__device__ __forceinline__ void mma16816(float c[4],
    unsigned a0, unsigned a1, unsigned a2, unsigned a3,
    unsigned b0, unsigned b1)
{
    asm volatile(
        "mma.sync.aligned.m16n8k16.row.col.f32.f16.f16.f32 "
        "{%0,%1,%2,%3},{%4,%5,%6,%7},{%8,%9},{%0,%1,%2,%3};\n"
        : "+f"(c[0]), "+f"(c[1]), "+f"(c[2]), "+f"(c[3])
        : "r"(a0), "r"(a1), "r"(a2), "r"(a3), "r"(b0), "r"(b1));
}

// ---------------- A' (emb|h1 part of gates1) via HMMA, no smem, no syncs ---
// J in [0,256): b0sel=J>>7, n=J&127. Out: g_g1p[b0sel][n][16 ci][64 r] fp32
__device__ __forceinline__ void aprime_job(int J, int tnext, int tid) {
    const int b0sel = J >> 7;
    const int n = J & 127;
    const int w = tid >> 5, lane = tid & 31;
    const int g = lane >> 2, tig = lane & 3;
    const int b_glob = b0sel*64 + w*8 + g;

    const uint4* wpn = (const uint4*)g_W1h + (size_t)n*NKC*32 + lane;
    const __half* embp = g_embh + ((size_t)tnext*BB + b_glob)*HID + tig*2;
    const __half* h1p  = g_h1h + (size_t)b_glob*H1S + tig*2;

    float cA[4] = {0.f, 0.f, 0.f, 0.f};
    float cB[4] = {0.f, 0.f, 0.f, 0.f};

    // emb region: kc 0..15
    #pragma unroll
    for (int kc = 0; kc < 16; kc += 2) {
        uint4 a = wpn[(size_t)kc*32];
        const unsigned* xp = (const unsigned*)(embp + kc*16);
        mma16816(cA, a.x, a.y, a.z, a.w, xp[0], xp[4]);
        uint4 a2 = wpn[(size_t)(kc+1)*32];
        const unsigned* xp2 = (const unsigned*)(embp + (kc+1)*16);
        mma16816(cB, a2.x, a2.y, a2.z, a2.w, xp2[0], xp2[4]);
    }
    // h1 region: kc 16..47
    #pragma unroll 4
    for (int kc = 16; kc < NKC; kc += 2) {
        uint4 a = wpn[(size_t)kc*32];
        const unsigned* xp = (const unsigned*)(h1p + (kc-16)*16);
        mma16816(cA, a.x, a.y, a.z, a.w, xp[0], xp[4]);
        uint4 a2 = wpn[(size_t)(kc+1)*32];
        const unsigned* xp2 = (const unsigned*)(h1p + (kc-15)*16);
        mma16816(cB, a2.x, a2.y, a2.z, a2.w, xp2[0], xp2[4]);
    }

    float* dst = g_g1p + ((size_t)b0sel*128 + n)*1024;
    int r_off = w*8 + tig*2;
    float2 lo = make_float2(cA[0]+cB[0], cA[1]+cB[1]);
    float2 hi = make_float2(cA[2]+cB[2], cA[3]+cB[3]);
    *(float2*)&dst[g*64 + r_off]       = lo;   // ci = g
    *(float2*)&dst[(g+8)*64 + r_off]   = hi;   // ci = g+8
}

// =============================================================================
// Persistent decoder kernel
// =============================================================================
__global__ __launch_bounds__(NTHR, 2) void decoder_kernel(
    const float* __restrict__ keys, const float* __restrict__ values,
    const int* __restrict__ lens, const int* __restrict__ text,
    const float* __restrict__ emb_table,
    const float* __restrict__ Wih1, const float* __restrict__ Whh1,
    const float* __restrict__ bih1, const float* __restrict__ bhh1,
    const float* __restrict__ Wih2, const float* __restrict__ Whh2,
    const float* __restrict__ bih2, const float* __restrict__ bhh2)
{
    __shared__ float sm[4160];
    const int tid = threadIdx.x;
    const int bid = blockIdx.x;
    const int gid = bid * NTHR + tid;
    const int gstride = NBLK * NTHR;   // 75776
    unsigned nb = 0, nbB = 0;

    // ---------------- pre-stage ----------------
    for (int i = gid; i < H1S*BB; i += gstride) {
        g_h1T[i] = 0.f; g_c1T[i] = 0.f; g_h1h[i] = __float2half_rn(0.f);
    }
    for (int i = gid; i < 2*KEY*BB; i += gstride) ((float*)g_h2T)[i] = 0.f;
    for (int i = gid; i < KEY*BB;   i += gstride) g_c2T[i] = 0.f;
    for (int i = gid; i < VAL*BB;   i += gstride) g_ctxT[i] = 0.f;

    // embedding gather -> fp16 [t][b][h] (writes coalesced over h)
    for (int i = gid; i < T_DEC*BB*HID; i += gstride) {
        int h = i & (HID-1);
        int r = i >> 8;            // t*BB + b
        int b = r & (BB-1);
        int t = r >> 7;
        g_embh[i] = __float2half_rn(emb_table[text[b*T_DEC + t]*HID + h]);
    }

    // pack W1 fp32 -> [128 tiles][896 k][16 cols] (A'' ctx part uses k 256..383)
    for (int i = gid; i < 128*896*16; i += gstride) {
        int ci = i & 15;
        int k  = (i >> 4) % 896;
        int n  = i / (896*16);
        int c  = n*4 + (ci & 3) + H1S * (ci >> 2);
        g_W1p[i] = (k < HID+VAL) ? Wih1[c*(HID+VAL) + k]
                                 : Whh1[c*H1S + (k - HID - VAL)];
    }
    // pack W1 fp16 mma A-fragments: [n 128][kc 48][lane 32][8 halves]
    for (int i = gid; i < 128*NKC*32*8; i += gstride) {
        int idx  = i & 7;
        int lane = (i >> 3) & 31;
        int kc   = (i >> 8) % NKC;
        int n    = i / (NKC*256);
        int g_   = lane >> 2, tig = lane & 3;
        int r_   = idx >> 1, h_ = idx & 1;
        int m    = g_ + ((r_ & 1) ? 8 : 0);
        int kadd = (r_ >= 2) ? 8 : 0;
        int k_local = kc*16 + tig*2 + h_ + kadd;      // 0..767 (emb|h1)
        int c = n*4 + (m & 3) + H1S * (m >> 2);
        int k_global = (k_local < HID) ? k_local : k_local + VAL; // skip ctx
        float v = (k_global < HID+VAL) ? Wih1[c*(HID+VAL) + k_global]
                                       : Whh1[c*H1S + (k_global - HID - VAL)];
        g_W1h[i] = __float2half_rn(v);
    }
    // pack W2 -> [32 tiles][640 k][16 cols]
    for (int i = gid; i < 32*640*16; i += gstride) {
        int ci = i & 15;
        int k  = (i >> 4) % 640;
        int n  = i / (640*16);
        int c  = n*4 + (ci & 3) + KEY * (ci >> 2);
        g_W2p[i] = (k < H1S) ? Wih2[c*H1S + k] : Whh2[c*KEY + (k - H1S)];
    }

    // convert V to fp16 ([t][b][v] layout kept)
    {
        const int n4 = (T_ENC*BB*VAL) / 4;
        const float4* v4 = (const float4*)values;
        __half2* vh2 = (__half2*)g_vh;
        for (int i = gid; i < n4; i += gstride) {
            float4 f = v4[i];
            vh2[2*i]   = __floats2half2_rn(f.x, f.y);
            vh2[2*i+1] = __floats2half2_rn(f.z, f.w);
        }
    }

    // transpose K -> fp16 [b][k][t] via smem tiles (64 t x 32 k per job)
    for (int j = bid; j < 128*4*32; j += NBLK) {
        int b  = j >> 7;
        int kt = (j >> 5) & 3;
        int tt = j & 31;
        float* st = sm;           // [64][33]
        #pragma unroll
        for (int p8 = 0; p8 < 8; p8++) {
            int trow = p8*8 + (tid >> 5);
            int kcol = tid & 31;
            st[trow*33 + kcol] =
                keys[((size_t)(tt*64 + trow)*BB + b)*KEY + kt*32 + kcol];
        }
        __syncthreads();
        #pragma unroll
        for (int p4 = 0; p4 < 8; p4++) {
            int kr   = p4*4 + (tid >> 6);
            int tcol = tid & 63;
            g_khT[((size_t)b*KEY + kt*32 + kr)*T_ENC + tt*64 + tcol] =
                __float2half_rn(st[tcol*33 + kr]);
        }
        __syncthreads();
    }
    nb++; gbar(bid, nb);

    // ---------------- A'_0: partial gates for t=0 (h1h = 0) ----------------
    if (bid < 256) aprime_job(bid, 0, tid);
    nb++; gbar(bid, nb);

    // ================= decode loop =================
    for (int t = 0; t < T_DEC; t++) {
        const int p = t & 1, pn = p ^ 1;

        // ---------- Interval 1: A'' = ctx-part GEMM (K=128) + cell1 ----------
        if (bid < 256) {
            const int b0 = (bid >> 7) * 64;
            const int n  = bid & 127;
            const int j0 = n * 4;
            const int q  = tid >> 6;          // 32 k per quadrant
            const int qt = tid & 63;
            const int r4 = (qt & 15) * 4;
            const int c4 = (qt >> 4) * 4;
            const float* Wp = g_W1p + (size_t)n * (896*16);
            float acc[4][4];
            #pragma unroll
            for (int i = 0; i < 4; i++)
                #pragma unroll
                for (int jj = 0; jj < 4; jj++) acc[i][jj] = 0.f;

            float* As = sm;           // [4][8][64]
            float* Bs = sm + 2048;    // [4][8][16]

            for (int it = 0; it < 4; it++) {
                #pragma unroll
                for (int i = 0; i < 8; i++) {
                    int li = i*256 + tid;
                    int k = (li >> 9)*32 + it*8 + ((li >> 6) & 7);
                    As[(li >> 9)*512 + ((li >> 6) & 7)*64 + (li & 63)] =
                        g_ctxT[k*BB + b0 + (li & 63)];
                }
                #pragma unroll
                for (int i = 0; i < 2; i++) {
                    int li = i*256 + tid;
                    int k = (li >> 7)*32 + it*8 + ((li >> 4) & 7);
                    Bs[(li >> 7)*128 + ((li >> 4) & 7)*16 + (li & 15)] =
                        Wp[(HID + k)*16 + (li & 15)];
                }
                __syncthreads();
                #pragma unroll
                for (int kk = 0; kk < 8; kk++) {
                    float4 a  = *(float4*)&As[q*512 + kk*64 + r4];
                    float4 bq = *(float4*)&Bs[q*128 + kk*16 + c4];
                    float av[4] = {a.x, a.y, a.z, a.w};
                    float bv[4] = {bq.x, bq.y, bq.z, bq.w};
                    #pragma unroll
                    for (int i = 0; i < 4; i++)
                        #pragma unroll
                        for (int jj = 0; jj < 4; jj++)
                            acc[i][jj] += av[i] * bv[jj];
                }
                __syncthreads();
            }
            float* red = sm;  // [4][1024]
            #pragma unroll
            for (int i = 0; i < 4; i++)
                *(float4*)&red[q*1024 + (r4+i)*16 + c4] =
                    make_float4(acc[i][0], acc[i][1], acc[i][2], acc[i][3]);
            __syncthreads();
            {   // epilogue: A' partial + ctx-part + bias -> cell1
                int r = tid & 63, jj = tid >> 6;
                const float* par = g_g1p + ((size_t)(bid >> 7)*128 + n)*1024;
                float gsum[4];
                #pragma unroll
                for (int g = 0; g < 4; g++) {
                    int ci = jj + 4*g;
                    float s = par[ci*64 + r];
                    #pragma unroll
                    for (int qq = 0; qq < 4; qq++)
                        s += red[qq*1024 + r*16 + ci];
                    gsum[g] = s;
                }
                int b = b0 + r, j = j0 + jj;
                float gi = gsum[0] + bih1[j]         + bhh1[j];
                float gf = gsum[1] + bih1[j +   H1S] + bhh1[j +   H1S];
                float gg = gsum[2] + bih1[j + 2*H1S] + bhh1[j + 2*H1S];
                float go = gsum[3] + bih1[j + 3*H1S] + bhh1[j + 3*H1S];
                int idx = j*BB + b;
                float c = sigf(gf) * g_c1T[idx] + sigf(gi) * tanhf(gg);
                g_c1T[idx] = c;
                float h = sigf(go) * tanhf(c);
                g_h1T[idx] = h;                         // fp32 [j][b]
                g_h1h[(size_t)b*H1S + j] = __float2half_rn(h);  // fp16 [b][j]
            }
        }
        nb++; gbar(bid, nb);

        // ---------- Interval 2: {B -> barB -> C} on 0-127 || A'_{t+1} -------
        if (bid < 128) {
            // ----- Stage B: gemm2 + cell2 -----
            const int b0 = (bid >> 5) * 32;
            const int n  = bid & 31;
            const int j0 = n * 4;
            const int q  = tid >> 6;          // 160 k per quadrant
            const int qt = tid & 63;
            const int r2 = (qt & 15) * 2;
            const int c4 = (qt >> 4) * 4;
            const float* Wp = g_W2p + (size_t)n * (640*16);
            float acc[2][4];
            #pragma unroll
            for (int i = 0; i < 2; i++)
                #pragma unroll
                for (int jj = 0; jj < 4; jj++) acc[i][jj] = 0.f;

            float* As = sm;           // [4][8][32]
            float* Bs = sm + 1024;    // [4][8][16]
            float ra[4], rb[2];

            #pragma unroll
            for (int i = 0; i < 4; i++) {
                int li = i*256 + tid;
                int k = (li >> 8)*160 + ((li >> 5) & 7);
                int b = b0 + (li & 31);
                ra[i] = (k < H1S) ? g_h1T[k*BB + b]
                                  : g_h2T[p][(k - H1S)*BB + b];
            }
            #pragma unroll
            for (int i = 0; i < 2; i++) {
                int li = i*256 + tid;
                int k = (li >> 7)*160 + ((li >> 4) & 7);
                rb[i] = Wp[k*16 + (li & 15)];
            }

            for (int it = 0; it < 20; it++) {
                #pragma unroll
                for (int i = 0; i < 4; i++) {
                    int li = i*256 + tid;
                    As[(li >> 8)*256 + ((li >> 5) & 7)*32 + (li & 31)] = ra[i];
                }
                #pragma unroll
                for (int i = 0; i < 2; i++) {
                    int li = i*256 + tid;
                    Bs[(li >> 7)*128 + ((li >> 4) & 7)*16 + (li & 15)] = rb[i];
                }
                __syncthreads();
                if (it < 19) {
                    #pragma unroll
                    for (int i = 0; i < 4; i++) {
                        int li = i*256 + tid;
                        int k = (li >> 8)*160 + (it+1)*8 + ((li >> 5) & 7);
                        int b = b0 + (li & 31);
                        ra[i] = (k < H1S) ? g_h1T[k*BB + b]
                                          : g_h2T[p][(k - H1S)*BB + b];
                    }
                    #pragma unroll
                    for (int i = 0; i < 2; i++) {
                        int li = i*256 + tid;
                        int k = (li >> 7)*160 + (it+1)*8 + ((li >> 4) & 7);
                        rb[i] = Wp[k*16 + (li & 15)];
                    }
                }
                #pragma unroll
                for (int kk = 0; kk < 8; kk++) {
                    float2 a  = *(float2*)&As[q*256 + kk*32 + r2];
                    float4 bq = *(float4*)&Bs[q*128 + kk*16 + c4];
                    float av[2] = {a.x, a.y};
                    float bv[4] = {bq.x, bq.y, bq.z, bq.w};
                    #pragma unroll
                    for (int i = 0; i < 2; i++)
                        #pragma unroll
                        for (int jj = 0; jj < 4; jj++)
                            acc[i][jj] += av[i] * bv[jj];
                }
                __syncthreads();
            }
            float* red = sm;  // [4][512]
            #pragma unroll
            for (int i = 0; i < 2; i++)
                *(float4*)&red[q*512 + (r2+i)*16 + c4] =
                    make_float4(acc[i][0], acc[i][1], acc[i][2], acc[i][3]);
            __syncthreads();
            if (tid < 128) {   // 32 rows x 4 j
                int r = tid & 31, jj = tid >> 5;
                float gsum[4];
                #pragma unroll
                for (int g = 0; g < 4; g++) {
                    float s = 0.f;
                    #pragma unroll
                    for (int qq = 0; qq < 4; qq++)
                        s += red[qq*512 + r*16 + jj + 4*g];
                    gsum[g] = s;
                }
                int b = b0 + r, j = j0 + jj;
                float gi = gsum[0] + bih2[j]         + bhh2[j];
                float gf = gsum[1] + bih2[j +   KEY] + bhh2[j +   KEY];
                float gg = gsum[2] + bih2[j + 2*KEY] + bhh2[j + 2*KEY];
                float go = gsum[3] + bih2[j + 3*KEY] + bhh2[j + 3*KEY];
                int idx = j*BB + b;
                float c = sigf(gf) * g_c2T[idx] + sigf(gi) * tanhf(gg);
                g_c2T[idx] = c;
                float h = sigf(go) * tanhf(c);
                g_h2T[pn][idx] = h;
                g_h2ctxT[(size_t)j*NROWS + t*BB + b] = h;
            }
            nbB++; barB(bid, nbB);

            // ----- Stage C: attention, two-pass smem softmax -----
            {
                const int b = bid;
                const int lane = tid & 31, w = tid >> 5;
                const int len = lens[b];
                float* s_p  = sm;           // [2048]
                float* s_pt = sm + 2048;    // [8][128]
                float* s_h2 = sm + 3072;    // [128]
                float* s_r  = sm + 3200;    // [16]
                if (tid < 128) s_h2[tid] = g_h2T[pn][tid*BB + b];
                __syncthreads();

                const int t0 = tid * 8;
                float ef[8];
                #pragma unroll
                for (int i = 0; i < 8; i++) ef[i] = 0.f;
                if (t0 < len) {
                    const __half* kp = g_khT + (size_t)b*KEY*T_ENC + t0;
                    #pragma unroll 4
                    for (int k = 0; k < KEY; k++) {
                        uint4 u = *(const uint4*)(kp + (size_t)k*T_ENC);
                        float h = s_h2[k];
                        float2 f0 = __half22float2(((__half2*)&u)[0]);
                        float2 f1 = __half22float2(((__half2*)&u)[1]);
                        float2 f2 = __half22float2(((__half2*)&u)[2]);
                        float2 f3 = __half22float2(((__half2*)&u)[3]);
                        ef[0] += h*f0.x; ef[1] += h*f0.y;
                        ef[2] += h*f1.x; ef[3] += h*f1.y;
                        ef[4] += h*f2.x; ef[5] += h*f2.y;
                        ef[6] += h*f3.x; ef[7] += h*f3.y;
                    }
                }
                float e[8];
                #pragma unroll
                for (int i = 0; i < 8; i++)
                    e[i] = (t0 + i < len) ? ef[i] : -3.0e38f;

                float tm = e[0];
                #pragma unroll
                for (int i = 1; i < 8; i++) tm = fmaxf(tm, e[i]);
                #pragma unroll
                for (int off = 16; off; off >>= 1)
                    tm = fmaxf(tm, __shfl_xor_sync(~0u, tm, off));
                if (lane == 0) s_r[w] = tm;
                __syncthreads();
                float M = s_r[0];
                #pragma unroll
                for (int ww = 1; ww < 8; ww++) M = fmaxf(M, s_r[ww]);

                float pv[8];
                float lsum = 0.f;
                #pragma unroll
                for (int i = 0; i < 8; i++) {
                    pv[i] = expf(e[i] - M);
                    lsum += pv[i];
                }
                *(float4*)&s_p[t0]     = make_float4(pv[0], pv[1], pv[2], pv[3]);
                *(float4*)&s_p[t0 + 4] = make_float4(pv[4], pv[5], pv[6], pv[7]);
                #pragma unroll
                for (int off = 16; off; off >>= 1)
                    lsum += __shfl_xor_sync(~0u, lsum, off);
                if (lane == 0) s_r[8 + w] = lsum;
                __syncthreads();
                float L = 0.f;
                #pragma unroll
                for (int ww = 0; ww < 8; ww++) L += s_r[8 + ww];
                const float Linv = 1.f / L;

                const int vq = (tid & 31) * 4;
                const int tg = tid >> 5;
                float a0 = 0.f, a1 = 0.f, a2 = 0.f, a3 = 0.f;
                const int itmax = (len + 7) >> 3;
                for (int it = 0; it < itmax; it++) {
                    int tt = it*8 + tg;
                    float pw = s_p[tt];
                    uint2 u = *(const uint2*)(g_vh + ((size_t)tt*BB + b)*VAL + vq);
                    float2 f01 = __half22float2(((__half2*)&u)[0]);
                    float2 f23 = __half22float2(((__half2*)&u)[1]);
                    a0 += pw*f01.x; a1 += pw*f01.y;
                    a2 += pw*f23.x; a3 += pw*f23.y;
                }
                *(float4*)&s_pt[tg*128 + vq] = make_float4(a0, a1, a2, a3);
                __syncthreads();
                if (tid < 128) {
                    float s = 0.f;
                    #pragma unroll
                    for (int g8 = 0; g8 < 8; g8++) s += s_pt[g8*128 + tid];
                    float cx = s * Linv;
                    g_ctxT[tid*BB + b] = cx;
                    g_h2ctxT[(size_t)(KEY + tid)*NROWS + t*BB + b] = cx;
                }
            }
        } else if (t + 1 < T_DEC) {
            // ----- A'_{t+1} on blocks 128-295 (static, 256 jobs) -----
            int i = bid - 128;                 // 0..167
            aprime_job(i, t + 1, tid);
            if (i < 88) aprime_job(168 + i, t + 1, tid);
        }
        nb++; gbar(bid, nb);
    }
}

// ---------------- final logits GEMM -------------
__global__ __launch_bounds__(256) void pred_kernel(
    const float* __restrict__ Wlin, const float* __restrict__ blin,
    float* __restrict__ out)
{
    __shared__ float As[16][68];
    __shared__ float Bs[16][68];
    const int r0 = blockIdx.x * 64;
    const int v0 = blockIdx.y * 64;
    const int tid = threadIdx.x;
    const int m0 = (tid & 15) * 4;
    const int n0 = (tid >> 4) * 4;
    float acc[4][4] = {};

    for (int k0 = 0; k0 < 256; k0 += 16) {
        #pragma unroll
        for (int i = 0; i < 4; i++) {
            int li = i*256 + tid;
            int kk = li >> 6, m = li & 63;
            As[kk][m] = g_h2ctxT[(size_t)(k0 + kk)*NROWS + r0 + m];
        }
        #pragma unroll
        for (int i = 0; i < 4; i++) {
            int li = i*256 + tid;
            int n = li >> 4, kk = li & 15;
            int v = v0 + n;
            Bs[kk][n] = (v < VOCAB) ? Wlin[v*256 + k0 + kk] : 0.f;
        }
        __syncthreads();
        #pragma unroll
        for (int kk = 0; kk < 16; kk++) {
            float4 a = *(const float4*)&As[kk][m0];
            float4 bq = *(const float4*)&Bs[kk][n0];
            float av[4] = {a.x, a.y, a.z, a.w};
            float bv[4] = {bq.x, bq.y, bq.z, bq.w};
            #pragma unroll
            for (int i = 0; i < 4; i++)
                #pragma unroll
                for (int j = 0; j < 4; j++)
                    acc[i][j] += av[i] * bv[j];
        }
        __syncthreads();
    }
    #pragma unroll
    for (int i = 0; i < 4; i++) {
        int r = r0 + m0 + i;
        int b = r & 127, t = r >> 7;
        #pragma unroll
        for (int j = 0; j < 4; j++) {
            int v = v0 + n0 + j;
            if (v < VOCAB)
                out[((size_t)b*T_DEC + t)*VOCAB + v] = acc[i][j] + blin[v];
        }
    }
}

// ---------------- launch (decoder FIRST so ncu -s 5 lands on it) ---------
extern "C" void kernel_launch(void* const* d_in, const int* in_sizes, int n_in,
                              void* d_out, int out_size)
{
    const float* keys      = (const float*)d_in[0];
    const float* values    = (const float*)d_in[1];
    const int*   lens      = (const int*)  d_in[2];
    const int*   text      = (const int*)  d_in[3];
    const float* emb_table = (const float*)d_in[4];
    const float* Wih1      = (const float*)d_in[5];
    const float* Whh1      = (const float*)d_in[6];
    const float* bih1      = (const float*)d_in[7];
    const float* bhh1      = (const float*)d_in[8];
    const float* Wih2      = (const float*)d_in[9];
    const float* Whh2      = (const float*)d_in[10];
    const float* bih2      = (const float*)d_in[11];
    const float* bhh2      = (const float*)d_in[12];
    const float* Wlin      = (const float*)d_in[13];
    const float* blin      = (const float*)d_in[14];
    float* out = (float*)d_out;

    // Barrier counters are statically zero-initialized; reset_bar_kernel at the
    // END of each launch restores that invariant for the next graph replay.
    decoder_kernel<<<NBLK, NTHR>>>(keys, values, lens, text, emb_table,
                                   Wih1, Whh1, bih1, bhh1,
                                   Wih2, Whh2, bih2, bhh2);
    pred_kernel<<<dim3(NROWS/64, (VOCAB + 63)/64), 256>>>(Wlin, blin, out);
    reset_bar_kernel<<<1, 512>>>();
}

// round 13
// speedup vs baseline: 1.1088x; 1.0629x over previous
#include <cuda_runtime.h>
#include <cuda_fp16.h>
#include <math.h>
#include <stdio.h>

#define BB 128       // batch
#define T_ENC 2048
#define T_DEC 256
#define HID 256
#define KEY 128
#define VAL 128
#define H1S 512      // lstm1 hidden
#define VOCAB 1000
#define NBLK 296     // 2 CTAs/SM * 148 SMs, all resident
#define NTHR 256
#define NROWS (T_DEC*BB)   // 32768
#define NKC 48       // k-chunks of 16 over K=768 (emb 256 | h1 512)

// ---------------- device scratch (static) ----------------
__device__ unsigned g_leaf[8*64];    // gbar-all leaves (256B apart)
__device__ unsigned g_root;
__device__ unsigned g_leafB[4*64];   // barB leaves (blocks 0-127)
__device__ unsigned g_rootB;
__device__ float g_h2ctxT[(size_t)(KEY+VAL)*NROWS];     // [f][t*BB+b]
__device__ float g_h1T[H1S*BB];                         // [j][b] fp32 (stage B)
__device__ float g_c1T[H1S*BB];
__device__ float g_h2T[2][KEY*BB];
__device__ float g_c2T[KEY*BB];
__device__ float g_ctxT[VAL*BB];                        // [v][b]
__device__ float g_g1p[(size_t)2*128*16*64];            // [b0sel][n][ci][r]
__device__ float g_W1p[(size_t)128*896*16];             // fp32 pack (A'' ctx part)
__device__ float g_W2p[(size_t)32*640*16];
__device__ __align__(16) __half g_W1h[(size_t)128*NKC*32*8]; // mma A-frag pack
__device__ __align__(16) __half g_embh[(size_t)T_DEC*BB*HID]; // [t][b][h] fp16
__device__ __align__(16) __half g_h1h[BB*H1S];               // [b][j] fp16
__device__ __align__(16) __half g_khT[(size_t)BB*KEY*T_ENC];  // [b][k][t]
__device__ __align__(16) __half g_vh[(size_t)T_ENC*BB*VAL];   // [t][b][v]

// ---------------- barriers (monotonic, hierarchical) ----------------
__device__ __forceinline__ void gbar(int bid, unsigned ph) {
    __syncthreads();
    if (threadIdx.x == 0) {
        __threadfence();
        int g = bid & 7;                       // 37 blocks per leaf
        unsigned old = atomicAdd(&g_leaf[g*64], 1u);
        if (old == ph*37u - 1u) atomicAdd(&g_root, 1u);
        while (*(volatile unsigned*)&g_root < ph*8u) __nanosleep(32);
        __threadfence();
    }
    __syncthreads();
}
// barrier among blocks 0..127 only
__device__ __forceinline__ void barB(int bid, unsigned ph) {
    __syncthreads();
    if (threadIdx.x == 0) {
        __threadfence();
        int g = bid & 3;                       // 32 blocks per leaf
        unsigned old = atomicAdd(&g_leafB[g*64], 1u);
        if (old == ph*32u - 1u) atomicAdd(&g_rootB, 1u);
        while (*(volatile unsigned*)&g_rootB < ph*4u) __nanosleep(32);
        __threadfence();
    }
    __syncthreads();
}

__global__ void reset_bar_kernel() {
    int i = threadIdx.x;
    if (i < 8*64) g_leaf[i] = 0u;
    if (i < 4*64) g_leafB[i] = 0u;
    if (i == 0) { g_root = 0u; g_rootB = 0u; }
}

__device__ __forceinline__ float sigf(float x) { return 1.f / (1.f + expf(-x)); }

__device__ __forceinline__ void mma16816(float c[4],
    unsigned a0, unsigned a1, unsigned a2, unsigned a3,
    unsigned b0, unsigned b1)
{
    asm volatile(
        "mma.sync.aligned.m16n8k16.row.col.f32.f16.f16.f32 "
        "{%0,%1,%2,%3},{%4,%5,%6,%7},{%8,%9},{%0,%1,%2,%3};\n"
        : "+f"(c[0]), "+f"(c[1]), "+f"(c[2]), "+f"(c[3])
        : "r"(a0), "r"(a1), "r"(a2), "r"(a3), "r"(b0), "r"(b1));
}

// stage timers: smem slots (long long) at sm[4096..], tid0 only
#define TMARK(sm_, slot) do { if (tid == 0) { \
    long long now_ = clock64(); \
    ((long long*)((sm_) + 4096))[slot] += now_ - tlast; tlast = now_; } } while(0)

// ---------------- A' (emb|h1 part of gates1) via HMMA, no smem, no syncs ---
// J in [0,256): b0sel=J>>7, n=J&127. Out: g_g1p[b0sel][n][16 ci][64 r] fp32
__device__ __forceinline__ void aprime_job(int J, int tnext, int tid) {
    const int b0sel = J >> 7;
    const int n = J & 127;
    const int w = tid >> 5, lane = tid & 31;
    const int g = lane >> 2, tig = lane & 3;
    const int b_glob = b0sel*64 + w*8 + g;

    const uint4* wpn = (const uint4*)g_W1h + (size_t)n*NKC*32 + lane;
    const __half* embp = g_embh + ((size_t)tnext*BB + b_glob)*HID + tig*2;
    const __half* h1p  = g_h1h + (size_t)b_glob*H1S + tig*2;

    float cA[4] = {0.f, 0.f, 0.f, 0.f};
    float cB[4] = {0.f, 0.f, 0.f, 0.f};

    // emb region: kc 0..15
    #pragma unroll
    for (int kc = 0; kc < 16; kc += 2) {
        uint4 a = wpn[(size_t)kc*32];
        const unsigned* xp = (const unsigned*)(embp + kc*16);
        mma16816(cA, a.x, a.y, a.z, a.w, xp[0], xp[4]);
        uint4 a2 = wpn[(size_t)(kc+1)*32];
        const unsigned* xp2 = (const unsigned*)(embp + (kc+1)*16);
        mma16816(cB, a2.x, a2.y, a2.z, a2.w, xp2[0], xp2[4]);
    }
    // h1 region: kc 16..47
    #pragma unroll 4
    for (int kc = 16; kc < NKC; kc += 2) {
        uint4 a = wpn[(size_t)kc*32];
        const unsigned* xp = (const unsigned*)(h1p + (kc-16)*16);
        mma16816(cA, a.x, a.y, a.z, a.w, xp[0], xp[4]);
        uint4 a2 = wpn[(size_t)(kc+1)*32];
        const unsigned* xp2 = (const unsigned*)(h1p + (kc-15)*16);
        mma16816(cB, a2.x, a2.y, a2.z, a2.w, xp2[0], xp2[4]);
    }

    float* dst = g_g1p + ((size_t)b0sel*128 + n)*1024;
    int r_off = w*8 + tig*2;
    float2 lo = make_float2(cA[0]+cB[0], cA[1]+cB[1]);
    float2 hi = make_float2(cA[2]+cB[2], cA[3]+cB[3]);
    *(float2*)&dst[g*64 + r_off]       = lo;   // ci = g
    *(float2*)&dst[(g+8)*64 + r_off]   = hi;   // ci = g+8
}

// =============================================================================
// Persistent decoder kernel
// =============================================================================
__global__ __launch_bounds__(NTHR, 2) void decoder_kernel(
    const float* __restrict__ keys, const float* __restrict__ values,
    const int* __restrict__ lens, const int* __restrict__ text,
    const float* __restrict__ emb_table,
    const float* __restrict__ Wih1, const float* __restrict__ Whh1,
    const float* __restrict__ bih1, const float* __restrict__ bhh1,
    const float* __restrict__ Wih2, const float* __restrict__ Whh2,
    const float* __restrict__ bih2, const float* __restrict__ bhh2)
{
    __shared__ float sm[4160];
    const int tid = threadIdx.x;
    const int bid = blockIdx.x;
    const int gid = bid * NTHR + tid;
    const int gstride = NBLK * NTHR;   // 75776
    unsigned nb = 0, nbB = 0;

    // ---------------- pre-stage ----------------
    for (int i = gid; i < H1S*BB; i += gstride) {
        g_h1T[i] = 0.f; g_c1T[i] = 0.f; g_h1h[i] = __float2half_rn(0.f);
    }
    for (int i = gid; i < 2*KEY*BB; i += gstride) ((float*)g_h2T)[i] = 0.f;
    for (int i = gid; i < KEY*BB;   i += gstride) g_c2T[i] = 0.f;
    for (int i = gid; i < VAL*BB;   i += gstride) g_ctxT[i] = 0.f;

    // embedding gather -> fp16 [t][b][h] (writes coalesced over h)
    for (int i = gid; i < T_DEC*BB*HID; i += gstride) {
        int h = i & (HID-1);
        int r = i >> 8;            // t*BB + b
        int b = r & (BB-1);
        int t = r >> 7;
        g_embh[i] = __float2half_rn(emb_table[text[b*T_DEC + t]*HID + h]);
    }

    // pack W1 fp32 -> [128 tiles][896 k][16 cols] (A'' ctx part uses k 256..383)
    for (int i = gid; i < 128*896*16; i += gstride) {
        int ci = i & 15;
        int k  = (i >> 4) % 896;
        int n  = i / (896*16);
        int c  = n*4 + (ci & 3) + H1S * (ci >> 2);
        g_W1p[i] = (k < HID+VAL) ? Wih1[c*(HID+VAL) + k]
                                 : Whh1[c*H1S + (k - HID - VAL)];
    }
    // pack W1 fp16 mma A-fragments: [n 128][kc 48][lane 32][8 halves]
    for (int i = gid; i < 128*NKC*32*8; i += gstride) {
        int idx  = i & 7;
        int lane = (i >> 3) & 31;
        int kc   = (i >> 8) % NKC;
        int n    = i / (NKC*256);
        int g_   = lane >> 2, tig = lane & 3;
        int r_   = idx >> 1, h_ = idx & 1;
        int m    = g_ + ((r_ & 1) ? 8 : 0);
        int kadd = (r_ >= 2) ? 8 : 0;
        int k_local = kc*16 + tig*2 + h_ + kadd;      // 0..767 (emb|h1)
        int c = n*4 + (m & 3) + H1S * (m >> 2);
        int k_global = (k_local < HID) ? k_local : k_local + VAL; // skip ctx
        float v = (k_global < HID+VAL) ? Wih1[c*(HID+VAL) + k_global]
                                       : Whh1[c*H1S + (k_global - HID - VAL)];
        g_W1h[i] = __float2half_rn(v);
    }
    // pack W2 -> [32 tiles][640 k][16 cols]
    for (int i = gid; i < 32*640*16; i += gstride) {
        int ci = i & 15;
        int k  = (i >> 4) % 640;
        int n  = i / (640*16);
        int c  = n*4 + (ci & 3) + KEY * (ci >> 2);
        g_W2p[i] = (k < H1S) ? Wih2[c*H1S + k] : Whh2[c*KEY + (k - H1S)];
    }

    // convert V to fp16 ([t][b][v] layout kept)
    {
        const int n4 = (T_ENC*BB*VAL) / 4;
        const float4* v4 = (const float4*)values;
        __half2* vh2 = (__half2*)g_vh;
        for (int i = gid; i < n4; i += gstride) {
            float4 f = v4[i];
            vh2[2*i]   = __floats2half2_rn(f.x, f.y);
            vh2[2*i+1] = __floats2half2_rn(f.z, f.w);
        }
    }

    // transpose K -> fp16 [b][k][t] via smem tiles (64 t x 32 k per job)
    for (int j = bid; j < 128*4*32; j += NBLK) {
        int b  = j >> 7;
        int kt = (j >> 5) & 3;
        int tt = j & 31;
        float* st = sm;           // [64][33]
        #pragma unroll
        for (int p8 = 0; p8 < 8; p8++) {
            int trow = p8*8 + (tid >> 5);
            int kcol = tid & 31;
            st[trow*33 + kcol] =
                keys[((size_t)(tt*64 + trow)*BB + b)*KEY + kt*32 + kcol];
        }
        __syncthreads();
        #pragma unroll
        for (int p4 = 0; p4 < 8; p4++) {
            int kr   = p4*4 + (tid >> 6);
            int tcol = tid & 63;
            g_khT[((size_t)b*KEY + kt*32 + kr)*T_ENC + tt*64 + tcol] =
                __float2half_rn(st[tcol*33 + kr]);
        }
        __syncthreads();
    }
    nb++; gbar(bid, nb);

    // ---------------- A'_0: partial gates for t=0 (h1h = 0) ----------------
    if (bid < 256) aprime_job(bid, 0, tid);
    nb++; gbar(bid, nb);

    // init stage timers
    if (tid == 0) {
        #pragma unroll
        for (int s = 0; s < 8; s++) ((long long*)(sm + 4096))[s] = 0;
    }
    __syncthreads();
    long long tlast = clock64();

    // ================= decode loop =================
    for (int t = 0; t < T_DEC; t++) {
        const int p = t & 1, pn = p ^ 1;

        // ---------- Interval 1: A'' = ctx-part GEMM (K=128) + cell1 ----------
        if (bid < 256) {
            const int b0 = (bid >> 7) * 64;
            const int n  = bid & 127;
            const int j0 = n * 4;
            const int q  = tid >> 6;          // 32 k per quadrant
            const int qt = tid & 63;
            const int r4 = (qt & 15) * 4;
            const int c4 = (qt >> 4) * 4;
            const float* Wp = g_W1p + (size_t)n * (896*16);
            float acc[4][4];
            #pragma unroll
            for (int i = 0; i < 4; i++)
                #pragma unroll
                for (int jj = 0; jj < 4; jj++) acc[i][jj] = 0.f;

            float* As = sm;           // [4][8][64]
            float* Bs = sm + 2048;    // [4][8][16]

            for (int it = 0; it < 4; it++) {
                #pragma unroll
                for (int i = 0; i < 8; i++) {
                    int li = i*256 + tid;
                    int k = (li >> 9)*32 + it*8 + ((li >> 6) & 7);
                    As[(li >> 9)*512 + ((li >> 6) & 7)*64 + (li & 63)] =
                        g_ctxT[k*BB + b0 + (li & 63)];
                }
                #pragma unroll
                for (int i = 0; i < 2; i++) {
                    int li = i*256 + tid;
                    int k = (li >> 7)*32 + it*8 + ((li >> 4) & 7);
                    Bs[(li >> 7)*128 + ((li >> 4) & 7)*16 + (li & 15)] =
                        Wp[(HID + k)*16 + (li & 15)];
                }
                __syncthreads();
                #pragma unroll
                for (int kk = 0; kk < 8; kk++) {
                    float4 a  = *(float4*)&As[q*512 + kk*64 + r4];
                    float4 bq = *(float4*)&Bs[q*128 + kk*16 + c4];
                    float av[4] = {a.x, a.y, a.z, a.w};
                    float bv[4] = {bq.x, bq.y, bq.z, bq.w};
                    #pragma unroll
                    for (int i = 0; i < 4; i++)
                        #pragma unroll
                        for (int jj = 0; jj < 4; jj++)
                            acc[i][jj] += av[i] * bv[jj];
                }
                __syncthreads();
            }
            float* red = sm;  // [4][1024]
            #pragma unroll
            for (int i = 0; i < 4; i++)
                *(float4*)&red[q*1024 + (r4+i)*16 + c4] =
                    make_float4(acc[i][0], acc[i][1], acc[i][2], acc[i][3]);
            __syncthreads();
            {   // epilogue: A' partial + ctx-part + bias -> cell1
                int r = tid & 63, jj = tid >> 6;
                const float* par = g_g1p + ((size_t)(bid >> 7)*128 + n)*1024;
                float gsum[4];
                #pragma unroll
                for (int g = 0; g < 4; g++) {
                    int ci = jj + 4*g;
                    float s = par[ci*64 + r];
                    #pragma unroll
                    for (int qq = 0; qq < 4; qq++)
                        s += red[qq*1024 + r*16 + ci];
                    gsum[g] = s;
                }
                int b = b0 + r, j = j0 + jj;
                float gi = gsum[0] + bih1[j]         + bhh1[j];
                float gf = gsum[1] + bih1[j +   H1S] + bhh1[j +   H1S];
                float gg = gsum[2] + bih1[j + 2*H1S] + bhh1[j + 2*H1S];
                float go = gsum[3] + bih1[j + 3*H1S] + bhh1[j + 3*H1S];
                int idx = j*BB + b;
                float c = sigf(gf) * g_c1T[idx] + sigf(gi) * tanhf(gg);
                g_c1T[idx] = c;
                float h = sigf(go) * tanhf(c);
                g_h1T[idx] = h;                         // fp32 [j][b]
                g_h1h[(size_t)b*H1S + j] = __float2half_rn(h);  // fp16 [b][j]
            }
        }
        TMARK(sm, 0);
        nb++; gbar(bid, nb);
        TMARK(sm, 1);

        // ---------- Interval 2: {B -> barB -> C} on 0-127 || A'_{t+1} -------
        if (bid < 128) {
            // ----- Stage B: gemm2 + cell2 (depth-2 register pipeline) -----
            const int b0 = (bid >> 5) * 32;
            const int n  = bid & 31;
            const int j0 = n * 4;
            const int q  = tid >> 6;          // 160 k per quadrant
            const int qt = tid & 63;
            const int r2 = (qt & 15) * 2;
            const int c4 = (qt >> 4) * 4;
            const float* Wp = g_W2p + (size_t)n * (640*16);
            float acc[2][4];
            #pragma unroll
            for (int i = 0; i < 2; i++)
                #pragma unroll
                for (int jj = 0; jj < 4; jj++) acc[i][jj] = 0.f;

            float* As = sm;           // [4][8][32]
            float* Bs = sm + 1024;    // [4][8][16]
            float ra0[4], rb0[2], ra1[4], rb1[2];

#define B_LOAD(RA, RB, ITV) do { \
            _Pragma("unroll") \
            for (int i_ = 0; i_ < 4; i_++) { \
                int li_ = i_*256 + tid; \
                int k_ = (li_ >> 8)*160 + (ITV)*8 + ((li_ >> 5) & 7); \
                int b_ = b0 + (li_ & 31); \
                (RA)[i_] = (k_ < H1S) ? g_h1T[k_*BB + b_] \
                                      : g_h2T[p][(k_ - H1S)*BB + b_]; \
            } \
            _Pragma("unroll") \
            for (int i_ = 0; i_ < 2; i_++) { \
                int li_ = i_*256 + tid; \
                int k_ = (li_ >> 7)*160 + (ITV)*8 + ((li_ >> 4) & 7); \
                (RB)[i_] = Wp[k_*16 + (li_ & 15)]; \
            } } while (0)

#define B_STORE(RA, RB) do { \
            _Pragma("unroll") \
            for (int i_ = 0; i_ < 4; i_++) { \
                int li_ = i_*256 + tid; \
                As[(li_ >> 8)*256 + ((li_ >> 5) & 7)*32 + (li_ & 31)] = (RA)[i_]; \
            } \
            _Pragma("unroll") \
            for (int i_ = 0; i_ < 2; i_++) { \
                int li_ = i_*256 + tid; \
                Bs[(li_ >> 7)*128 + ((li_ >> 4) & 7)*16 + (li_ & 15)] = (RB)[i_]; \
            } } while (0)

#define B_COMPUTE() do { \
            _Pragma("unroll") \
            for (int kk_ = 0; kk_ < 8; kk_++) { \
                float2 a_  = *(float2*)&As[q*256 + kk_*32 + r2]; \
                float4 bq_ = *(float4*)&Bs[q*128 + kk_*16 + c4]; \
                float av_[2] = {a_.x, a_.y}; \
                float bv_[4] = {bq_.x, bq_.y, bq_.z, bq_.w}; \
                _Pragma("unroll") \
                for (int i_ = 0; i_ < 2; i_++) \
                    _Pragma("unroll") \
                    for (int jj_ = 0; jj_ < 4; jj_++) \
                        acc[i_][jj_] += av_[i_] * bv_[jj_]; \
            } } while (0)

            B_LOAD(ra0, rb0, 0);
            B_LOAD(ra1, rb1, 1);
            for (int it = 0; it < 20; it += 2) {
                B_STORE(ra0, rb0);
                __syncthreads();
                if (it + 2 < 20) B_LOAD(ra0, rb0, it + 2);
                B_COMPUTE();
                __syncthreads();
                B_STORE(ra1, rb1);
                __syncthreads();
                if (it + 3 < 20) B_LOAD(ra1, rb1, it + 3);
                B_COMPUTE();
                __syncthreads();
            }
            float* red = sm;  // [4][512]
            #pragma unroll
            for (int i = 0; i < 2; i++)
                *(float4*)&red[q*512 + (r2+i)*16 + c4] =
                    make_float4(acc[i][0], acc[i][1], acc[i][2], acc[i][3]);
            __syncthreads();
            if (tid < 128) {   // 32 rows x 4 j
                int r = tid & 31, jj = tid >> 5;
                float gsum[4];
                #pragma unroll
                for (int g = 0; g < 4; g++) {
                    float s = 0.f;
                    #pragma unroll
                    for (int qq = 0; qq < 4; qq++)
                        s += red[qq*512 + r*16 + jj + 4*g];
                    gsum[g] = s;
                }
                int b = b0 + r, j = j0 + jj;
                float gi = gsum[0] + bih2[j]         + bhh2[j];
                float gf = gsum[1] + bih2[j +   KEY] + bhh2[j +   KEY];
                float gg = gsum[2] + bih2[j + 2*KEY] + bhh2[j + 2*KEY];
                float go = gsum[3] + bih2[j + 3*KEY] + bhh2[j + 3*KEY];
                int idx = j*BB + b;
                float c = sigf(gf) * g_c2T[idx] + sigf(gi) * tanhf(gg);
                g_c2T[idx] = c;
                float h = sigf(go) * tanhf(c);
                g_h2T[pn][idx] = h;
                g_h2ctxT[(size_t)j*NROWS + t*BB + b] = h;
            }
            TMARK(sm, 2);
            nbB++; barB(bid, nbB);
            TMARK(sm, 3);

            // ----- Stage C: attention, two-pass smem softmax -----
            {
                const int b = bid;
                const int lane = tid & 31, w = tid >> 5;
                const int len = lens[b];
                float* s_p  = sm;           // [2048]
                float* s_pt = sm + 2048;    // [8][128]
                float* s_h2 = sm + 3072;    // [128]
                float* s_r  = sm + 3200;    // [16]
                if (tid < 128) s_h2[tid] = g_h2T[pn][tid*BB + b];
                __syncthreads();

                const int t0 = tid * 8;
                float ef[8];
                #pragma unroll
                for (int i = 0; i < 8; i++) ef[i] = 0.f;
                if (t0 < len) {
                    const __half* kp = g_khT + (size_t)b*KEY*T_ENC + t0;
                    #pragma unroll 8
                    for (int k = 0; k < KEY; k++) {
                        uint4 u = *(const uint4*)(kp + (size_t)k*T_ENC);
                        float h = s_h2[k];
                        float2 f0 = __half22float2(((__half2*)&u)[0]);
                        float2 f1 = __half22float2(((__half2*)&u)[1]);
                        float2 f2 = __half22float2(((__half2*)&u)[2]);
                        float2 f3 = __half22float2(((__half2*)&u)[3]);
                        ef[0] += h*f0.x; ef[1] += h*f0.y;
                        ef[2] += h*f1.x; ef[3] += h*f1.y;
                        ef[4] += h*f2.x; ef[5] += h*f2.y;
                        ef[6] += h*f3.x; ef[7] += h*f3.y;
                    }
                }
                float e[8];
                #pragma unroll
                for (int i = 0; i < 8; i++)
                    e[i] = (t0 + i < len) ? ef[i] : -3.0e38f;

                float tm = e[0];
                #pragma unroll
                for (int i = 1; i < 8; i++) tm = fmaxf(tm, e[i]);
                #pragma unroll
                for (int off = 16; off; off >>= 1)
                    tm = fmaxf(tm, __shfl_xor_sync(~0u, tm, off));
                if (lane == 0) s_r[w] = tm;
                __syncthreads();
                float M = s_r[0];
                #pragma unroll
                for (int ww = 1; ww < 8; ww++) M = fmaxf(M, s_r[ww]);

                float pv[8];
                float lsum = 0.f;
                #pragma unroll
                for (int i = 0; i < 8; i++) {
                    pv[i] = expf(e[i] - M);
                    lsum += pv[i];
                }
                *(float4*)&s_p[t0]     = make_float4(pv[0], pv[1], pv[2], pv[3]);
                *(float4*)&s_p[t0 + 4] = make_float4(pv[4], pv[5], pv[6], pv[7]);
                #pragma unroll
                for (int off = 16; off; off >>= 1)
                    lsum += __shfl_xor_sync(~0u, lsum, off);
                if (lane == 0) s_r[8 + w] = lsum;
                __syncthreads();
                float L = 0.f;
                #pragma unroll
                for (int ww = 0; ww < 8; ww++) L += s_r[8 + ww];
                const float Linv = 1.f / L;

                // --- V pass: chunk-4 double-buffered pipeline ---
                const int vq = (tid & 31) * 4;
                const int tg = tid >> 5;
                float a0 = 0.f, a1 = 0.f, a2 = 0.f, a3 = 0.f;
                const int itmax = (len + 7) >> 3;
                const int nc = (itmax + 3) >> 2;       // chunks of 4 iters
                uint2 bufA[4], bufB[4];
                const __half* vbase = g_vh + (size_t)b*VAL + vq;

#define V_LOAD(BUF, CH) do { \
                int itb_ = (CH)*4; \
                _Pragma("unroll") \
                for (int i_ = 0; i_ < 4; i_++) { \
                    int tt_ = (itb_ + i_)*8 + tg; \
                    (BUF)[i_] = *(const uint2*)(vbase + (size_t)tt_*BB*VAL); \
                } } while (0)

#define V_COMP(BUF, CH) do { \
                int itb_ = (CH)*4; \
                _Pragma("unroll") \
                for (int i_ = 0; i_ < 4; i_++) { \
                    int tt_ = (itb_ + i_)*8 + tg; \
                    float pw_ = s_p[tt_]; \
                    float2 f01_ = __half22float2(((__half2*)&(BUF)[i_])[0]); \
                    float2 f23_ = __half22float2(((__half2*)&(BUF)[i_])[1]); \
                    a0 += pw_*f01_.x; a1 += pw_*f01_.y; \
                    a2 += pw_*f23_.x; a3 += pw_*f23_.y; \
                } } while (0)

                V_LOAD(bufA, 0);
                if (nc > 1) V_LOAD(bufB, 1);
                for (int ch = 0; ch < nc; ch += 2) {
                    V_COMP(bufA, ch);
                    if (ch + 2 < nc) V_LOAD(bufA, ch + 2);
                    if (ch + 1 < nc) {
                        V_COMP(bufB, ch + 1);
                        if (ch + 3 < nc) V_LOAD(bufB, ch + 3);
                    }
                }
                *(float4*)&s_pt[tg*128 + vq] = make_float4(a0, a1, a2, a3);
                __syncthreads();
                if (tid < 128) {
                    float s = 0.f;
                    #pragma unroll
                    for (int g8 = 0; g8 < 8; g8++) s += s_pt[g8*128 + tid];
                    float cx = s * Linv;
                    g_ctxT[tid*BB + b] = cx;
                    g_h2ctxT[(size_t)(KEY + tid)*NROWS + t*BB + b] = cx;
                }
            }
            TMARK(sm, 4);
        } else {
            if (t + 1 < T_DEC) {
                // ----- A'_{t+1} on blocks 128-295 (static, 256 jobs) -----
                int i = bid - 128;                 // 0..167
                aprime_job(i, t + 1, tid);
                if (i < 88) aprime_job(168 + i, t + 1, tid);
            }
            TMARK(sm, 2);
        }
        nb++; gbar(bid, nb);
        TMARK(sm, 5);
    }

    // stage-timer dump (once per launch; goes to stdout/log only)
    __syncthreads();
    if (tid == 0 && (bid == 0 || bid == 150)) {
        long long* tt = (long long*)(sm + 4096);
        printf("BLK%d: s0=%lld s1=%lld s2=%lld s3=%lld s4=%lld s5=%lld\n",
               bid, tt[0], tt[1], tt[2], tt[3], tt[4], tt[5]);
    }
}

// ---------------- final logits GEMM -------------
__global__ __launch_bounds__(256) void pred_kernel(
    const float* __restrict__ Wlin, const float* __restrict__ blin,
    float* __restrict__ out)
{
    __shared__ float As[16][68];
    __shared__ float Bs[16][68];
    const int r0 = blockIdx.x * 64;
    const int v0 = blockIdx.y * 64;
    const int tid = threadIdx.x;
    const int m0 = (tid & 15) * 4;
    const int n0 = (tid >> 4) * 4;
    float acc[4][4] = {};

    for (int k0 = 0; k0 < 256; k0 += 16) {
        #pragma unroll
        for (int i = 0; i < 4; i++) {
            int li = i*256 + tid;
            int kk = li >> 6, m = li & 63;
            As[kk][m] = g_h2ctxT[(size_t)(k0 + kk)*NROWS + r0 + m];
        }
        #pragma unroll
        for (int i = 0; i < 4; i++) {
            int li = i*256 + tid;
            int n = li >> 4, kk = li & 15;
            int v = v0 + n;
            Bs[kk][n] = (v < VOCAB) ? Wlin[v*256 + k0 + kk] : 0.f;
        }
        __syncthreads();
        #pragma unroll
        for (int kk = 0; kk < 16; kk++) {
            float4 a = *(const float4*)&As[kk][m0];
            float4 bq = *(const float4*)&Bs[kk][n0];
            float av[4] = {a.x, a.y, a.z, a.w};
            float bv[4] = {bq.x, bq.y, bq.z, bq.w};
            #pragma unroll
            for (int i = 0; i < 4; i++)
                #pragma unroll
                for (int j = 0; j < 4; j++)
                    acc[i][j] += av[i] * bv[j];
        }
        __syncthreads();
    }
    #pragma unroll
    for (int i = 0; i < 4; i++) {
        int r = r0 + m0 + i;
        int b = r & 127, t = r >> 7;
        #pragma unroll
        for (int j = 0; j < 4; j++) {
            int v = v0 + n0 + j;
            if (v < VOCAB)
                out[((size_t)b*T_DEC + t)*VOCAB + v] = acc[i][j] + blin[v];
        }
    }
}

// ---------------- launch (decoder FIRST so ncu -s 5 lands on it) ---------
extern "C" void kernel_launch(void* const* d_in, const int* in_sizes, int n_in,
                              void* d_out, int out_size)
{
    const float* keys      = (const float*)d_in[0];
    const float* values    = (const float*)d_in[1];
    const int*   lens      = (const int*)  d_in[2];
    const int*   text      = (const int*)  d_in[3];
    const float* emb_table = (const float*)d_in[4];
    const float* Wih1      = (const float*)d_in[5];
    const float* Whh1      = (const float*)d_in[6];
    const float* bih1      = (const float*)d_in[7];
    const float* bhh1      = (const float*)d_in[8];
    const float* Wih2      = (const float*)d_in[9];
    const float* Whh2      = (const float*)d_in[10];
    const float* bih2      = (const float*)d_in[11];
    const float* bhh2      = (const float*)d_in[12];
    const float* Wlin      = (const float*)d_in[13];
    const float* blin      = (const float*)d_in[14];
    float* out = (float*)d_out;

    // Barrier counters are statically zero-initialized; reset_bar_kernel at the
    // END of each launch restores that invariant for the next graph replay.
    decoder_kernel<<<NBLK, NTHR>>>(keys, values, lens, text, emb_table,
                                   Wih1, Whh1, bih1, bhh1,
                                   Wih2, Whh2, bih2, bhh2);
    pred_kernel<<<dim3(NROWS/64, (VOCAB + 63)/64), 256>>>(Wlin, blin, out);
    reset_bar_kernel<<<1, 512>>>();
}

// round 14
// speedup vs baseline: 1.2469x; 1.1246x over previous
#include <cuda_runtime.h>
#include <cuda_fp16.h>
#include <math.h>

#define BB 128       // batch
#define T_ENC 2048
#define T_DEC 256
#define HID 256
#define KEY 128
#define VAL 128
#define H1S 512      // lstm1 hidden
#define VOCAB 1000
#define NBLK 296     // 2 CTAs/SM * 148 SMs, all resident
#define NTHR 256
#define NROWS (T_DEC*BB)   // 32768
#define NKC 48       // k-chunks of 16 over K=768 (emb 256 | h1 512)

// ---------------- device scratch (static) ----------------
__device__ unsigned g_leaf[8*64];    // gbar-all leaves (256B apart)
__device__ unsigned g_root;
__device__ unsigned g_leafB[8*64];   // bar256 leaves (blocks 0-255)
__device__ unsigned g_rootB;
__device__ unsigned g_cflag[BB];     // attention combine flags (monotonic)
__device__ float g_att[2][BB][132];  // [chunk][b]: acc[0..128), m[128], l[129]
__device__ float g_h2ctxT[(size_t)(KEY+VAL)*NROWS];     // [f][t*BB+b]
__device__ float g_h1T[H1S*BB];                         // [j][b] fp32 (stage B)
__device__ float g_c1T[H1S*BB];
__device__ float g_h2T[2][KEY*BB];
__device__ float g_c2T[KEY*BB];
__device__ float g_ctxT[VAL*BB];                        // [v][b]
__device__ float g_g1p[(size_t)2*128*16*64];            // [b0sel][n][ci][r]
__device__ float g_W1p[(size_t)128*896*16];             // fp32 pack (A'' ctx part)
__device__ float g_W2p[(size_t)32*640*16];
__device__ __align__(16) __half g_W1h[(size_t)128*NKC*32*8]; // mma A-frag pack
__device__ __align__(16) __half g_embh[(size_t)T_DEC*BB*HID]; // [t][b][h] fp16
__device__ __align__(16) __half g_h1h[BB*H1S];               // [b][j] fp16
__device__ __align__(16) __half g_khT[(size_t)BB*KEY*T_ENC];  // [b][k][t]
__device__ __align__(16) __half g_vh[(size_t)T_ENC*BB*VAL];   // [t][b][v]

// ---------------- barriers (monotonic, hierarchical) ----------------
__device__ __forceinline__ void gbar(int bid, unsigned ph) {
    __syncthreads();
    if (threadIdx.x == 0) {
        __threadfence();
        int g = bid & 7;                       // 37 blocks per leaf
        unsigned old = atomicAdd(&g_leaf[g*64], 1u);
        if (old == ph*37u - 1u) atomicAdd(&g_root, 1u);
        while (*(volatile unsigned*)&g_root < ph*8u) __nanosleep(32);
        __threadfence();
    }
    __syncthreads();
}
// barrier among blocks 0..255 only
__device__ __forceinline__ void bar256(int bid, unsigned ph) {
    __syncthreads();
    if (threadIdx.x == 0) {
        __threadfence();
        int g = bid & 7;                       // 32 blocks per leaf
        unsigned old = atomicAdd(&g_leafB[g*64], 1u);
        if (old == ph*32u - 1u) atomicAdd(&g_rootB, 1u);
        while (*(volatile unsigned*)&g_rootB < ph*8u) __nanosleep(32);
        __threadfence();
    }
    __syncthreads();
}

__global__ void reset_bar_kernel() {
    int i = threadIdx.x;
    if (i < 8*64) { g_leaf[i] = 0u; g_leafB[i] = 0u; }
    if (i < BB) g_cflag[i] = 0u;
    if (i == 0) { g_root = 0u; g_rootB = 0u; }
}

__device__ __forceinline__ float sigf(float x) { return 1.f / (1.f + expf(-x)); }

__device__ __forceinline__ void mma16816(float c[4],
    unsigned a0, unsigned a1, unsigned a2, unsigned a3,
    unsigned b0, unsigned b1)
{
    asm volatile(
        "mma.sync.aligned.m16n8k16.row.col.f32.f16.f16.f32 "
        "{%0,%1,%2,%3},{%4,%5,%6,%7},{%8,%9},{%0,%1,%2,%3};\n"
        : "+f"(c[0]), "+f"(c[1]), "+f"(c[2]), "+f"(c[3])
        : "r"(a0), "r"(a1), "r"(a2), "r"(a3), "r"(b0), "r"(b1));
}

// ---------------- A' (emb|h1 part of gates1) via HMMA, no smem, no syncs ---
// J in [0,256): b0sel=J>>7, n=J&127. Out: g_g1p[b0sel][n][16 ci][64 r] fp32
__device__ __forceinline__ void aprime_job(int J, int tnext, int tid) {
    const int b0sel = J >> 7;
    const int n = J & 127;
    const int w = tid >> 5, lane = tid & 31;
    const int g = lane >> 2, tig = lane & 3;
    const int b_glob = b0sel*64 + w*8 + g;

    const uint4* wpn = (const uint4*)g_W1h + (size_t)n*NKC*32 + lane;
    const __half* embp = g_embh + ((size_t)tnext*BB + b_glob)*HID + tig*2;
    const __half* h1p  = g_h1h + (size_t)b_glob*H1S + tig*2;

    float cA[4] = {0.f, 0.f, 0.f, 0.f};
    float cB[4] = {0.f, 0.f, 0.f, 0.f};

    // emb region: kc 0..15
    #pragma unroll
    for (int kc = 0; kc < 16; kc += 2) {
        uint4 a = wpn[(size_t)kc*32];
        const unsigned* xp = (const unsigned*)(embp + kc*16);
        mma16816(cA, a.x, a.y, a.z, a.w, xp[0], xp[4]);
        uint4 a2 = wpn[(size_t)(kc+1)*32];
        const unsigned* xp2 = (const unsigned*)(embp + (kc+1)*16);
        mma16816(cB, a2.x, a2.y, a2.z, a2.w, xp2[0], xp2[4]);
    }
    // h1 region: kc 16..47
    #pragma unroll 4
    for (int kc = 16; kc < NKC; kc += 2) {
        uint4 a = wpn[(size_t)kc*32];
        const unsigned* xp = (const unsigned*)(h1p + (kc-16)*16);
        mma16816(cA, a.x, a.y, a.z, a.w, xp[0], xp[4]);
        uint4 a2 = wpn[(size_t)(kc+1)*32];
        const unsigned* xp2 = (const unsigned*)(h1p + (kc-15)*16);
        mma16816(cB, a2.x, a2.y, a2.z, a2.w, xp2[0], xp2[4]);
    }

    float* dst = g_g1p + ((size_t)b0sel*128 + n)*1024;
    int r_off = w*8 + tig*2;
    float2 lo = make_float2(cA[0]+cB[0], cA[1]+cB[1]);
    float2 hi = make_float2(cA[2]+cB[2], cA[3]+cB[3]);
    *(float2*)&dst[g*64 + r_off]       = lo;   // ci = g
    *(float2*)&dst[(g+8)*64 + r_off]   = hi;   // ci = g+8
}

// =============================================================================
// Persistent decoder kernel
// =============================================================================
__global__ __launch_bounds__(NTHR, 2) void decoder_kernel(
    const float* __restrict__ keys, const float* __restrict__ values,
    const int* __restrict__ lens, const int* __restrict__ text,
    const float* __restrict__ emb_table,
    const float* __restrict__ Wih1, const float* __restrict__ Whh1,
    const float* __restrict__ bih1, const float* __restrict__ bhh1,
    const float* __restrict__ Wih2, const float* __restrict__ Whh2,
    const float* __restrict__ bih2, const float* __restrict__ bhh2)
{
    __shared__ float sm[4160];
    const int tid = threadIdx.x;
    const int bid = blockIdx.x;
    const int gid = bid * NTHR + tid;
    const int gstride = NBLK * NTHR;   // 75776
    unsigned nb = 0, nbB = 0;

    // ---------------- pre-stage ----------------
    for (int i = gid; i < H1S*BB; i += gstride) {
        g_h1T[i] = 0.f; g_c1T[i] = 0.f; g_h1h[i] = __float2half_rn(0.f);
    }
    for (int i = gid; i < 2*KEY*BB; i += gstride) ((float*)g_h2T)[i] = 0.f;
    for (int i = gid; i < KEY*BB;   i += gstride) g_c2T[i] = 0.f;
    for (int i = gid; i < VAL*BB;   i += gstride) g_ctxT[i] = 0.f;

    // embedding gather -> fp16 [t][b][h] (writes coalesced over h)
    for (int i = gid; i < T_DEC*BB*HID; i += gstride) {
        int h = i & (HID-1);
        int r = i >> 8;            // t*BB + b
        int b = r & (BB-1);
        int t = r >> 7;
        g_embh[i] = __float2half_rn(emb_table[text[b*T_DEC + t]*HID + h]);
    }

    // pack W1 fp32 -> [128 tiles][896 k][16 cols] (A'' ctx part uses k 256..383)
    for (int i = gid; i < 128*896*16; i += gstride) {
        int ci = i & 15;
        int k  = (i >> 4) % 896;
        int n  = i / (896*16);
        int c  = n*4 + (ci & 3) + H1S * (ci >> 2);
        g_W1p[i] = (k < HID+VAL) ? Wih1[c*(HID+VAL) + k]
                                 : Whh1[c*H1S + (k - HID - VAL)];
    }
    // pack W1 fp16 mma A-fragments: [n 128][kc 48][lane 32][8 halves]
    for (int i = gid; i < 128*NKC*32*8; i += gstride) {
        int idx  = i & 7;
        int lane = (i >> 3) & 31;
        int kc   = (i >> 8) % NKC;
        int n    = i / (NKC*256);
        int g_   = lane >> 2, tig = lane & 3;
        int r_   = idx >> 1, h_ = idx & 1;
        int m    = g_ + ((r_ & 1) ? 8 : 0);
        int kadd = (r_ >= 2) ? 8 : 0;
        int k_local = kc*16 + tig*2 + h_ + kadd;      // 0..767 (emb|h1)
        int c = n*4 + (m & 3) + H1S * (m >> 2);
        int k_global = (k_local < HID) ? k_local : k_local + VAL; // skip ctx
        float v = (k_global < HID+VAL) ? Wih1[c*(HID+VAL) + k_global]
                                       : Whh1[c*H1S + (k_global - HID - VAL)];
        g_W1h[i] = __float2half_rn(v);
    }
    // pack W2 -> [32 tiles][640 k][16 cols]
    for (int i = gid; i < 32*640*16; i += gstride) {
        int ci = i & 15;
        int k  = (i >> 4) % 640;
        int n  = i / (640*16);
        int c  = n*4 + (ci & 3) + KEY * (ci >> 2);
        g_W2p[i] = (k < H1S) ? Wih2[c*H1S + k] : Whh2[c*KEY + (k - H1S)];
    }

    // convert V to fp16 ([t][b][v] layout kept)
    {
        const int n4 = (T_ENC*BB*VAL) / 4;
        const float4* v4 = (const float4*)values;
        __half2* vh2 = (__half2*)g_vh;
        for (int i = gid; i < n4; i += gstride) {
            float4 f = v4[i];
            vh2[2*i]   = __floats2half2_rn(f.x, f.y);
            vh2[2*i+1] = __floats2half2_rn(f.z, f.w);
        }
    }

    // transpose K -> fp16 [b][k][t] via smem tiles (64 t x 32 k per job)
    for (int j = bid; j < 128*4*32; j += NBLK) {
        int b  = j >> 7;
        int kt = (j >> 5) & 3;
        int tt = j & 31;
        float* st = sm;           // [64][33]
        #pragma unroll
        for (int p8 = 0; p8 < 8; p8++) {
            int trow = p8*8 + (tid >> 5);
            int kcol = tid & 31;
            st[trow*33 + kcol] =
                keys[((size_t)(tt*64 + trow)*BB + b)*KEY + kt*32 + kcol];
        }
        __syncthreads();
        #pragma unroll
        for (int p4 = 0; p4 < 8; p4++) {
            int kr   = p4*4 + (tid >> 6);
            int tcol = tid & 63;
            g_khT[((size_t)b*KEY + kt*32 + kr)*T_ENC + tt*64 + tcol] =
                __float2half_rn(st[tcol*33 + kr]);
        }
        __syncthreads();
    }
    nb++; gbar(bid, nb);

    // ---------------- A'_0: partial gates for t=0 (h1h = 0) ----------------
    if (bid < 256) aprime_job(bid, 0, tid);
    nb++; gbar(bid, nb);

    // ================= decode loop =================
    for (int t = 0; t < T_DEC; t++) {
        const int p = t & 1, pn = p ^ 1;

        // ---------- Interval 1: A'' = ctx-part GEMM (K=128) + cell1 ----------
        if (bid < 256) {
            const int b0 = (bid >> 7) * 64;
            const int n  = bid & 127;
            const int j0 = n * 4;
            const int q  = tid >> 6;          // 32 k per quadrant
            const int qt = tid & 63;
            const int r4 = (qt & 15) * 4;
            const int c4 = (qt >> 4) * 4;
            const float* Wp = g_W1p + (size_t)n * (896*16);
            float acc[4][4];
            #pragma unroll
            for (int i = 0; i < 4; i++)
                #pragma unroll
                for (int jj = 0; jj < 4; jj++) acc[i][jj] = 0.f;

            float* As = sm;           // [4][8][64]
            float* Bs = sm + 2048;    // [4][8][16]

            for (int it = 0; it < 4; it++) {
                #pragma unroll
                for (int i = 0; i < 8; i++) {
                    int li = i*256 + tid;
                    int k = (li >> 9)*32 + it*8 + ((li >> 6) & 7);
                    As[(li >> 9)*512 + ((li >> 6) & 7)*64 + (li & 63)] =
                        g_ctxT[k*BB + b0 + (li & 63)];
                }
                #pragma unroll
                for (int i = 0; i < 2; i++) {
                    int li = i*256 + tid;
                    int k = (li >> 7)*32 + it*8 + ((li >> 4) & 7);
                    Bs[(li >> 7)*128 + ((li >> 4) & 7)*16 + (li & 15)] =
                        Wp[(HID + k)*16 + (li & 15)];
                }
                __syncthreads();
                #pragma unroll
                for (int kk = 0; kk < 8; kk++) {
                    float4 a  = *(float4*)&As[q*512 + kk*64 + r4];
                    float4 bq = *(float4*)&Bs[q*128 + kk*16 + c4];
                    float av[4] = {a.x, a.y, a.z, a.w};
                    float bv[4] = {bq.x, bq.y, bq.z, bq.w};
                    #pragma unroll
                    for (int i = 0; i < 4; i++)
                        #pragma unroll
                        for (int jj = 0; jj < 4; jj++)
                            acc[i][jj] += av[i] * bv[jj];
                }
                __syncthreads();
            }
            float* red = sm;  // [4][1024]
            #pragma unroll
            for (int i = 0; i < 4; i++)
                *(float4*)&red[q*1024 + (r4+i)*16 + c4] =
                    make_float4(acc[i][0], acc[i][1], acc[i][2], acc[i][3]);
            __syncthreads();
            {   // epilogue: A' partial + ctx-part + bias -> cell1
                int r = tid & 63, jj = tid >> 6;
                const float* par = g_g1p + ((size_t)(bid >> 7)*128 + n)*1024;
                float gsum[4];
                #pragma unroll
                for (int g = 0; g < 4; g++) {
                    int ci = jj + 4*g;
                    float s = par[ci*64 + r];
                    #pragma unroll
                    for (int qq = 0; qq < 4; qq++)
                        s += red[qq*1024 + r*16 + ci];
                    gsum[g] = s;
                }
                int b = b0 + r, j = j0 + jj;
                float gi = gsum[0] + bih1[j]         + bhh1[j];
                float gf = gsum[1] + bih1[j +   H1S] + bhh1[j +   H1S];
                float gg = gsum[2] + bih1[j + 2*H1S] + bhh1[j + 2*H1S];
                float go = gsum[3] + bih1[j + 3*H1S] + bhh1[j + 3*H1S];
                int idx = j*BB + b;
                float c = sigf(gf) * g_c1T[idx] + sigf(gi) * tanhf(gg);
                g_c1T[idx] = c;
                float h = sigf(go) * tanhf(c);
                g_h1T[idx] = h;                         // fp32 [j][b]
                g_h1h[(size_t)b*H1S + j] = __float2half_rn(h);  // fp16 [b][j]
            }
        }
        nb++; gbar(bid, nb);

        // ---------- Interval 2 ----------
        // blocks 0-127: B -> bar256 -> attention chunk0
        // blocks 128-255: A'(1-2) -> bar256 -> attention chunk1
        // blocks 256-295: A'(2) -> (step gbar)
        if (bid < 128) {
            // ----- Stage B: gemm2 + cell2 (depth-2 register pipeline) -----
            const int b0 = (bid >> 5) * 32;
            const int n  = bid & 31;
            const int j0 = n * 4;
            const int q  = tid >> 6;          // 160 k per quadrant
            const int qt = tid & 63;
            const int r2 = (qt & 15) * 2;
            const int c4 = (qt >> 4) * 4;
            const float* Wp = g_W2p + (size_t)n * (640*16);
            float acc[2][4];
            #pragma unroll
            for (int i = 0; i < 2; i++)
                #pragma unroll
                for (int jj = 0; jj < 4; jj++) acc[i][jj] = 0.f;

            float* As = sm;           // [4][8][32]
            float* Bs = sm + 1024;    // [4][8][16]
            float ra0[4], rb0[2], ra1[4], rb1[2];

#define B_LOAD(RA, RB, ITV) do { \
            _Pragma("unroll") \
            for (int i_ = 0; i_ < 4; i_++) { \
                int li_ = i_*256 + tid; \
                int k_ = (li_ >> 8)*160 + (ITV)*8 + ((li_ >> 5) & 7); \
                int b_ = b0 + (li_ & 31); \
                (RA)[i_] = (k_ < H1S) ? g_h1T[k_*BB + b_] \
                                      : g_h2T[p][(k_ - H1S)*BB + b_]; \
            } \
            _Pragma("unroll") \
            for (int i_ = 0; i_ < 2; i_++) { \
                int li_ = i_*256 + tid; \
                int k_ = (li_ >> 7)*160 + (ITV)*8 + ((li_ >> 4) & 7); \
                (RB)[i_] = Wp[k_*16 + (li_ & 15)]; \
            } } while (0)

#define B_STORE(RA, RB) do { \
            _Pragma("unroll") \
            for (int i_ = 0; i_ < 4; i_++) { \
                int li_ = i_*256 + tid; \
                As[(li_ >> 8)*256 + ((li_ >> 5) & 7)*32 + (li_ & 31)] = (RA)[i_]; \
            } \
            _Pragma("unroll") \
            for (int i_ = 0; i_ < 2; i_++) { \
                int li_ = i_*256 + tid; \
                Bs[(li_ >> 7)*128 + ((li_ >> 4) & 7)*16 + (li_ & 15)] = (RB)[i_]; \
            } } while (0)

#define B_COMPUTE() do { \
            _Pragma("unroll") \
            for (int kk_ = 0; kk_ < 8; kk_++) { \
                float2 a_  = *(float2*)&As[q*256 + kk_*32 + r2]; \
                float4 bq_ = *(float4*)&Bs[q*128 + kk_*16 + c4]; \
                float av_[2] = {a_.x, a_.y}; \
                float bv_[4] = {bq_.x, bq_.y, bq_.z, bq_.w}; \
                _Pragma("unroll") \
                for (int i_ = 0; i_ < 2; i_++) \
                    _Pragma("unroll") \
                    for (int jj_ = 0; jj_ < 4; jj_++) \
                        acc[i_][jj_] += av_[i_] * bv_[jj_]; \
            } } while (0)

            B_LOAD(ra0, rb0, 0);
            B_LOAD(ra1, rb1, 1);
            for (int it = 0; it < 20; it += 2) {
                B_STORE(ra0, rb0);
                __syncthreads();
                if (it + 2 < 20) B_LOAD(ra0, rb0, it + 2);
                B_COMPUTE();
                __syncthreads();
                B_STORE(ra1, rb1);
                __syncthreads();
                if (it + 3 < 20) B_LOAD(ra1, rb1, it + 3);
                B_COMPUTE();
                __syncthreads();
            }
            float* red = sm;  // [4][512]
            #pragma unroll
            for (int i = 0; i < 2; i++)
                *(float4*)&red[q*512 + (r2+i)*16 + c4] =
                    make_float4(acc[i][0], acc[i][1], acc[i][2], acc[i][3]);
            __syncthreads();
            if (tid < 128) {   // 32 rows x 4 j
                int r = tid & 31, jj = tid >> 5;
                float gsum[4];
                #pragma unroll
                for (int g = 0; g < 4; g++) {
                    float s = 0.f;
                    #pragma unroll
                    for (int qq = 0; qq < 4; qq++)
                        s += red[qq*512 + r*16 + jj + 4*g];
                    gsum[g] = s;
                }
                int b = b0 + r, j = j0 + jj;
                float gi = gsum[0] + bih2[j]         + bhh2[j];
                float gf = gsum[1] + bih2[j +   KEY] + bhh2[j +   KEY];
                float gg = gsum[2] + bih2[j + 2*KEY] + bhh2[j + 2*KEY];
                float go = gsum[3] + bih2[j + 3*KEY] + bhh2[j + 3*KEY];
                int idx = j*BB + b;
                float c = sigf(gf) * g_c2T[idx] + sigf(gi) * tanhf(gg);
                g_c2T[idx] = c;
                float h = sigf(go) * tanhf(c);
                g_h2T[pn][idx] = h;
                g_h2ctxT[(size_t)j*NROWS + t*BB + b] = h;
            }
        } else if (bid < 256) {
            // A': job (bid-128); blocks 208-255 also job 168+(bid-208)
            if (t + 1 < T_DEC) {
                aprime_job(bid - 128, t + 1, tid);
                if (bid >= 208) aprime_job(168 + (bid - 208), t + 1, tid);
            }
        } else {
            // blocks 256-295: jobs 128+(bid-256), 216+(bid-256)
            if (t + 1 < T_DEC) {
                aprime_job(128 + (bid - 256), t + 1, tid);
                aprime_job(216 + (bid - 256), t + 1, tid);
            }
        }

        if (bid < 256) {
            nbB++; bar256(bid, nbB);

            // ----- Attention (chunked): block handles b = bid&127, chunk = bid>>7
            const int b = bid & 127;
            const int chunk = bid >> 7;
            const int lane = tid & 31, w = tid >> 5;
            const int len = lens[b];
            const int c0 = chunk << 10;
            int lenc = len - c0; if (lenc > 1024) lenc = 1024;

            float* s_p  = sm;           // [1024]
            float* s_pt = sm + 1024;    // [8][128]
            float* s_h2 = sm + 2048;    // [128]
            float* s_r  = sm + 2176;    // [16]
            float* s_c  = sm + 2200;    // combine scratch
            if (tid < 128) s_h2[tid] = g_h2T[pn][tid*BB + b];
            __syncthreads();

            // --- E pass: thread owns 4 local t's; 4-way k-interleave ---
            const int t0 = tid * 4;
            float ef[4] = {0.f, 0.f, 0.f, 0.f};
            if (lenc > 0) {
                const __half* kp = g_khT + (size_t)b*KEY*T_ENC + c0 + t0;
                #pragma unroll 2
                for (int k = 0; k < KEY; k += 4) {
                    uint2 u0 = *(const uint2*)(kp + (size_t)k*T_ENC);
                    uint2 u1 = *(const uint2*)(kp + (size_t)(k+1)*T_ENC);
                    uint2 u2 = *(const uint2*)(kp + (size_t)(k+2)*T_ENC);
                    uint2 u3 = *(const uint2*)(kp + (size_t)(k+3)*T_ENC);
                    float h0 = s_h2[k], h1 = s_h2[k+1];
                    float h2v = s_h2[k+2], h3 = s_h2[k+3];
                    float2 a, bb;
                    a = __half22float2(((__half2*)&u0)[0]);
                    bb = __half22float2(((__half2*)&u0)[1]);
                    ef[0] += h0*a.x; ef[1] += h0*a.y; ef[2] += h0*bb.x; ef[3] += h0*bb.y;
                    a = __half22float2(((__half2*)&u1)[0]);
                    bb = __half22float2(((__half2*)&u1)[1]);
                    ef[0] += h1*a.x; ef[1] += h1*a.y; ef[2] += h1*bb.x; ef[3] += h1*bb.y;
                    a = __half22float2(((__half2*)&u2)[0]);
                    bb = __half22float2(((__half2*)&u2)[1]);
                    ef[0] += h2v*a.x; ef[1] += h2v*a.y; ef[2] += h2v*bb.x; ef[3] += h2v*bb.y;
                    a = __half22float2(((__half2*)&u3)[0]);
                    bb = __half22float2(((__half2*)&u3)[1]);
                    ef[0] += h3*a.x; ef[1] += h3*a.y; ef[2] += h3*bb.x; ef[3] += h3*bb.y;
                }
            }
            float e[4];
            #pragma unroll
            for (int i = 0; i < 4; i++)
                e[i] = (t0 + i < lenc) ? ef[i] : -3.0e38f;

            // --- chunk max ---
            float tm = fmaxf(fmaxf(e[0], e[1]), fmaxf(e[2], e[3]));
            #pragma unroll
            for (int off = 16; off; off >>= 1)
                tm = fmaxf(tm, __shfl_xor_sync(~0u, tm, off));
            if (lane == 0) s_r[w] = tm;
            __syncthreads();
            float M = s_r[0];
            #pragma unroll
            for (int ww = 1; ww < 8; ww++) M = fmaxf(M, s_r[ww]);

            float pv[4];
            float lsum = 0.f;
            #pragma unroll
            for (int i = 0; i < 4; i++) {
                pv[i] = expf(e[i] - M);
                lsum += pv[i];
            }
            *(float4*)&s_p[t0] = make_float4(pv[0], pv[1], pv[2], pv[3]);
            #pragma unroll
            for (int off = 16; off; off >>= 1)
                lsum += __shfl_xor_sync(~0u, lsum, off);
            if (lane == 0) s_r[8 + w] = lsum;
            __syncthreads();
            float L = 0.f;
            #pragma unroll
            for (int ww = 0; ww < 8; ww++) L += s_r[8 + ww];

            // --- V pass: chunk-4 double-buffered pipeline over local t range ---
            const int vq = (tid & 31) * 4;
            const int tg = tid >> 5;
            float a0 = 0.f, a1 = 0.f, a2 = 0.f, a3 = 0.f;
            if (lenc > 0) {
                const int itmax = (lenc + 7) >> 3;
                const int nc = (itmax + 3) >> 2;
                uint2 bufA[4], bufB[4];
                const __half* vbase = g_vh + ((size_t)c0*BB + b)*VAL + vq;

#define V_LOAD(BUF, CH) do { \
                int itb_ = (CH)*4; \
                _Pragma("unroll") \
                for (int i_ = 0; i_ < 4; i_++) { \
                    int tl_ = (itb_ + i_)*8 + tg; \
                    (BUF)[i_] = *(const uint2*)(vbase + (size_t)tl_*BB*VAL); \
                } } while (0)

#define V_COMP(BUF, CH) do { \
                int itb_ = (CH)*4; \
                _Pragma("unroll") \
                for (int i_ = 0; i_ < 4; i_++) { \
                    int tl_ = (itb_ + i_)*8 + tg; \
                    float pw_ = s_p[tl_]; \
                    float2 f01_ = __half22float2(((__half2*)&(BUF)[i_])[0]); \
                    float2 f23_ = __half22float2(((__half2*)&(BUF)[i_])[1]); \
                    a0 += pw_*f01_.x; a1 += pw_*f01_.y; \
                    a2 += pw_*f23_.x; a3 += pw_*f23_.y; \
                } } while (0)

                V_LOAD(bufA, 0);
                if (nc > 1) V_LOAD(bufB, 1);
                for (int ch = 0; ch < nc; ch += 2) {
                    V_COMP(bufA, ch);
                    if (ch + 2 < nc) V_LOAD(bufA, ch + 2);
                    if (ch + 1 < nc) {
                        V_COMP(bufB, ch + 1);
                        if (ch + 3 < nc) V_LOAD(bufB, ch + 3);
                    }
                }
            }
            *(float4*)&s_pt[tg*128 + vq] = make_float4(a0, a1, a2, a3);
            __syncthreads();
            // write partial (unnormalized acc + m + l)
            float* ap = (float*)&g_att[chunk][b][0];
            if (tid < 128) {
                float s = 0.f;
                #pragma unroll
                for (int g8 = 0; g8 < 8; g8++) s += s_pt[g8*128 + tid];
                ap[tid] = s;
            }
            if (tid == 0) { ap[128] = M; ap[129] = L; }
            __threadfence();
            __syncthreads();
            if (tid == 0) *(unsigned*)s_c = atomicAdd(&g_cflag[b], 1u);
            __syncthreads();
            if (*(unsigned*)s_c == 2u*(unsigned)t + 1u) {
                // this block is second: do the combine (deterministic math)
                __threadfence();
                float m0 = g_att[0][b][128], l0 = g_att[0][b][129];
                float m1 = g_att[1][b][128], l1 = g_att[1][b][129];
                float Mf = fmaxf(m0, m1);
                float w0 = expf(m0 - Mf), w1 = expf(m1 - Mf);
                float Linv = 1.f / (l0*w0 + l1*w1);
                if (tid < 128) {
                    float cx = (g_att[0][b][tid]*w0 + g_att[1][b][tid]*w1) * Linv;
                    g_ctxT[tid*BB + b] = cx;
                    g_h2ctxT[(size_t)(KEY + tid)*NROWS + t*BB + b] = cx;
                }
            }
        }
        nb++; gbar(bid, nb);
    }
}

// ---------------- final logits GEMM -------------
__global__ __launch_bounds__(256) void pred_kernel(
    const float* __restrict__ Wlin, const float* __restrict__ blin,
    float* __restrict__ out)
{
    __shared__ float As[16][68];
    __shared__ float Bs[16][68];
    const int r0 = blockIdx.x * 64;
    const int v0 = blockIdx.y * 64;
    const int tid = threadIdx.x;
    const int m0 = (tid & 15) * 4;
    const int n0 = (tid >> 4) * 4;
    float acc[4][4] = {};

    for (int k0 = 0; k0 < 256; k0 += 16) {
        #pragma unroll
        for (int i = 0; i < 4; i++) {
            int li = i*256 + tid;
            int kk = li >> 6, m = li & 63;
            As[kk][m] = g_h2ctxT[(size_t)(k0 + kk)*NROWS + r0 + m];
        }
        #pragma unroll
        for (int i = 0; i < 4; i++) {
            int li = i*256 + tid;
            int n = li >> 4, kk = li & 15;
            int v = v0 + n;
            Bs[kk][n] = (v < VOCAB) ? Wlin[v*256 + k0 + kk] : 0.f;
        }
        __syncthreads();
        #pragma unroll
        for (int kk = 0; kk < 16; kk++) {
            float4 a = *(const float4*)&As[kk][m0];
            float4 bq = *(const float4*)&Bs[kk][n0];
            float av[4] = {a.x, a.y, a.z, a.w};
            float bv[4] = {bq.x, bq.y, bq.z, bq.w};
            #pragma unroll
            for (int i = 0; i < 4; i++)
                #pragma unroll
                for (int j = 0; j < 4; j++)
                    acc[i][j] += av[i] * bv[j];
        }
        __syncthreads();
    }
    #pragma unroll
    for (int i = 0; i < 4; i++) {
        int r = r0 + m0 + i;
        int b = r & 127, t = r >> 7;
        #pragma unroll
        for (int j = 0; j < 4; j++) {
            int v = v0 + n0 + j;
            if (v < VOCAB)
                out[((size_t)b*T_DEC + t)*VOCAB + v] = acc[i][j] + blin[v];
        }
    }
}

// ---------------- launch (decoder FIRST so ncu -s 5 lands on it) ---------
extern "C" void kernel_launch(void* const* d_in, const int* in_sizes, int n_in,
                              void* d_out, int out_size)
{
    const float* keys      = (const float*)d_in[0];
    const float* values    = (const float*)d_in[1];
    const int*   lens      = (const int*)  d_in[2];
    const int*   text      = (const int*)  d_in[3];
    const float* emb_table = (const float*)d_in[4];
    const float* Wih1      = (const float*)d_in[5];
    const float* Whh1      = (const float*)d_in[6];
    const float* bih1      = (const float*)d_in[7];
    const float* bhh1      = (const float*)d_in[8];
    const float* Wih2      = (const float*)d_in[9];
    const float* Whh2      = (const float*)d_in[10];
    const float* bih2      = (const float*)d_in[11];
    const float* bhh2      = (const float*)d_in[12];
    const float* Wlin      = (const float*)d_in[13];
    const float* blin      = (const float*)d_in[14];
    float* out = (float*)d_out;

    // Barrier/flag counters are statically zero-initialized; reset_bar_kernel
    // at the END of each launch restores that invariant for the next replay.
    decoder_kernel<<<NBLK, NTHR>>>(keys, values, lens, text, emb_table,
                                   Wih1, Whh1, bih1, bhh1,
                                   Wih2, Whh2, bih2, bhh2);
    pred_kernel<<<dim3(NROWS/64, (VOCAB + 63)/64), 256>>>(Wlin, blin, out);
    reset_bar_kernel<<<1, 512>>>();
}

// round 17
// speedup vs baseline: 1.5203x; 1.2192x over previous
#include <cuda_runtime.h>
#include <cuda_fp16.h>
#include <math.h>

#define BB 128       // batch
#define T_ENC 2048
#define T_DEC 256
#define HID 256
#define KEY 128
#define VAL 128
#define H1S 512      // lstm1 hidden
#define VOCAB 1000
#define NBLK 296     // 2 CTAs/SM * 148 SMs, all resident
#define NTHR 256
#define NROWS (T_DEC*BB)   // 32768
#define NKC 48       // k-chunks of 16 over K=768 (emb 256 | h1 512)

// ---------------- device scratch (static) ----------------
__device__ unsigned g_leaf[8*64];    // gbar-all leaves (256B apart)
__device__ unsigned g_root;
__device__ unsigned g_leafB[8*64];   // bar256 leaves (blocks 0-255)
__device__ unsigned g_rootB;
__device__ unsigned g_cflag[BB];     // attention combine flags (monotonic)
__device__ float g_att[2][BB][132];  // [chunk][b]: acc[0..128), m[128], l[129]
__device__ float g_h2ctxT[(size_t)(KEY+VAL)*NROWS];     // [f][t*BB+b]
__device__ float g_c1T[H1S*BB];                         // [j][b]
__device__ float g_h2T[2][KEY*BB];                      // [j][b] fp32 (attn)
__device__ float g_c2T[KEY*BB];
__device__ float g_g1p[(size_t)2*128*16*64];            // [b0sel][n][ci][r]
__device__ __align__(16) __half g_W1h[(size_t)128*NKC*32*8];  // A' frag pack
__device__ __align__(16) __half g_W1ch[(size_t)128*8*32*8];   // A'' ctx frag pack
__device__ __align__(16) __half g_W2h[(size_t)32*40*32*8];    // B frag pack
__device__ __align__(16) __half g_embh[(size_t)T_DEC*BB*HID]; // [t][b][h] fp16
__device__ __align__(16) __half g_h1h[BB*H1S];               // [b][j] fp16
__device__ __align__(16) __half g_h2h[2][BB*KEY];            // [b][j] fp16
__device__ __align__(16) __half g_ctxh[BB*VAL];              // [b][v] fp16
__device__ __align__(16) __half g_khT[(size_t)BB*KEY*T_ENC];  // [b][k][t]
__device__ __align__(16) __half g_vh[(size_t)T_ENC*BB*VAL];   // [t][b][v]

// ---------------- barriers (monotonic, hierarchical) ----------------
__device__ __forceinline__ void gbar(int bid, unsigned ph) {
    __syncthreads();
    if (threadIdx.x == 0) {
        __threadfence();
        int g = bid & 7;                       // 37 blocks per leaf
        unsigned old = atomicAdd(&g_leaf[g*64], 1u);
        if (old == ph*37u - 1u) atomicAdd(&g_root, 1u);
        while (*(volatile unsigned*)&g_root < ph*8u) __nanosleep(32);
        __threadfence();
    }
    __syncthreads();
}
// barrier among blocks 0..255 only
__device__ __forceinline__ void bar256(int bid, unsigned ph) {
    __syncthreads();
    if (threadIdx.x == 0) {
        __threadfence();
        int g = bid & 7;                       // 32 blocks per leaf
        unsigned old = atomicAdd(&g_leafB[g*64], 1u);
        if (old == ph*32u - 1u) atomicAdd(&g_rootB, 1u);
        while (*(volatile unsigned*)&g_rootB < ph*8u) __nanosleep(32);
        __threadfence();
    }
    __syncthreads();
}

__global__ void reset_bar_kernel() {
    int i = threadIdx.x;
    if (i < 8*64) { g_leaf[i] = 0u; g_leafB[i] = 0u; }
    if (i < BB) g_cflag[i] = 0u;
    if (i == 0) { g_root = 0u; g_rootB = 0u; }
}

__device__ __forceinline__ float sigf(float x) { return 1.f / (1.f + expf(-x)); }

__device__ __forceinline__ void mma16816(float c[4],
    unsigned a0, unsigned a1, unsigned a2, unsigned a3,
    unsigned b0, unsigned b1)
{
    asm volatile(
        "mma.sync.aligned.m16n8k16.row.col.f32.f16.f16.f32 "
        "{%0,%1,%2,%3},{%4,%5,%6,%7},{%8,%9},{%0,%1,%2,%3};\n"
        : "+f"(c[0]), "+f"(c[1]), "+f"(c[2]), "+f"(c[3])
        : "r"(a0), "r"(a1), "r"(a2), "r"(a3), "r"(b0), "r"(b1));
}

// ---------------- A' (emb|h1 part of gates1) via HMMA ----------------------
// J in [0,256): b0sel=J>>7, n=J&127. Out: g_g1p[b0sel][n][16 ci][64 r] fp32
__device__ __forceinline__ void aprime_job(int J, int tnext, int tid) {
    const int b0sel = J >> 7;
    const int n = J & 127;
    const int w = tid >> 5, lane = tid & 31;
    const int g = lane >> 2, tig = lane & 3;
    const int b_glob = b0sel*64 + w*8 + g;

    const uint4* wpn = (const uint4*)g_W1h + (size_t)n*NKC*32 + lane;
    const __half* embp = g_embh + ((size_t)tnext*BB + b_glob)*HID + tig*2;
    const __half* h1p  = g_h1h + (size_t)b_glob*H1S + tig*2;

    float cA[4] = {0.f, 0.f, 0.f, 0.f};
    float cB[4] = {0.f, 0.f, 0.f, 0.f};

    #pragma unroll
    for (int kc = 0; kc < 16; kc += 2) {
        uint4 a = wpn[(size_t)kc*32];
        const unsigned* xp = (const unsigned*)(embp + kc*16);
        mma16816(cA, a.x, a.y, a.z, a.w, xp[0], xp[4]);
        uint4 a2 = wpn[(size_t)(kc+1)*32];
        const unsigned* xp2 = (const unsigned*)(embp + (kc+1)*16);
        mma16816(cB, a2.x, a2.y, a2.z, a2.w, xp2[0], xp2[4]);
    }
    #pragma unroll 4
    for (int kc = 16; kc < NKC; kc += 2) {
        uint4 a = wpn[(size_t)kc*32];
        const unsigned* xp = (const unsigned*)(h1p + (kc-16)*16);
        mma16816(cA, a.x, a.y, a.z, a.w, xp[0], xp[4]);
        uint4 a2 = wpn[(size_t)(kc+1)*32];
        const unsigned* xp2 = (const unsigned*)(h1p + (kc-15)*16);
        mma16816(cB, a2.x, a2.y, a2.z, a2.w, xp2[0], xp2[4]);
    }

    float* dst = g_g1p + ((size_t)b0sel*128 + n)*1024;
    int r_off = w*8 + tig*2;
    float2 lo = make_float2(cA[0]+cB[0], cA[1]+cB[1]);
    float2 hi = make_float2(cA[2]+cB[2], cA[3]+cB[3]);
    *(float2*)&dst[g*64 + r_off]       = lo;   // ci = g
    *(float2*)&dst[(g+8)*64 + r_off]   = hi;   // ci = g+8
}

// ---------------- A'' (ctx part) HMMA + partial-add + cell1 ----------------
// J in [0,256): b0sel=J>>7, n=J&127 (16 cols = 4 j x 4 gates)
__device__ __forceinline__ void aseg_job(int J, int tid,
    const float* __restrict__ bih1, const float* __restrict__ bhh1)
{
    const int b0sel = J >> 7;
    const int n = J & 127;
    const int w = tid >> 5, lane = tid & 31;
    const int g = lane >> 2, tig = lane & 3;
    const int b_glob = b0sel*64 + w*8 + g;

    const uint4* wpn = (const uint4*)g_W1ch + (size_t)n*8*32 + lane;
    const __half* xp0 = g_ctxh + (size_t)b_glob*VAL + tig*2;

    float cA[4] = {0.f, 0.f, 0.f, 0.f};
    float cB[4] = {0.f, 0.f, 0.f, 0.f};
    #pragma unroll
    for (int kc = 0; kc < 8; kc += 2) {
        uint4 a = wpn[(size_t)kc*32];
        const unsigned* xp = (const unsigned*)(xp0 + kc*16);
        mma16816(cA, a.x, a.y, a.z, a.w, xp[0], xp[4]);
        uint4 a2 = wpn[(size_t)(kc+1)*32];
        const unsigned* xp2 = (const unsigned*)(xp0 + (kc+1)*16);
        mma16816(cB, a2.x, a2.y, a2.z, a2.w, xp2[0], xp2[4]);
    }
    float v0 = cA[0]+cB[0], v1 = cA[1]+cB[1];
    float v2 = cA[2]+cB[2], v3 = cA[3]+cB[3];
    float u0 = __shfl_xor_sync(~0u, v0, 16);
    float u1 = __shfl_xor_sync(~0u, v1, 16);
    float u2 = __shfl_xor_sync(~0u, v2, 16);
    float u3 = __shfl_xor_sync(~0u, v3, 16);
    if (g < 4) {
        int j = n*4 + g;
        int rl = w*8 + tig*2;
        const float* par = g_g1p + ((size_t)b0sel*128 + n)*1024;
        float2 pi = *(const float2*)&par[( 0 + g)*64 + rl];
        float2 pf = *(const float2*)&par[( 4 + g)*64 + rl];
        float2 pg = *(const float2*)&par[( 8 + g)*64 + rl];
        float2 po = *(const float2*)&par[(12 + g)*64 + rl];
        float bi = bih1[j]         + bhh1[j];
        float bf = bih1[j +   H1S] + bhh1[j +   H1S];
        float bg = bih1[j + 2*H1S] + bhh1[j + 2*H1S];
        float bo = bih1[j + 3*H1S] + bhh1[j + 3*H1S];
        int b = b0sel*64 + rl;
        {
            float gi = v0 + pi.x + bi, gf = u0 + pf.x + bf;
            float gg = v2 + pg.x + bg, go = u2 + po.x + bo;
            int idx = j*BB + b;
            float c = sigf(gf)*g_c1T[idx] + sigf(gi)*tanhf(gg);
            g_c1T[idx] = c;
            g_h1h[(size_t)b*H1S + j] = __float2half_rn(sigf(go)*tanhf(c));
        }
        {
            float gi = v1 + pi.y + bi, gf = u1 + pf.y + bf;
            float gg = v3 + pg.y + bg, go = u3 + po.y + bo;
            int idx = j*BB + b + 1;
            float c = sigf(gf)*g_c1T[idx] + sigf(gi)*tanhf(gg);
            g_c1T[idx] = c;
            g_h1h[(size_t)(b+1)*H1S + j] = __float2half_rn(sigf(go)*tanhf(c));
        }
    }
}

// ---------------- Stage B HMMA + cell2 -------------------------------------
// bid in [0,64): b0sel=bid>>5, n=bid&31 (16 cols = 4 j x 4 gates), K=640
__device__ __forceinline__ void bstage_job(int bid, int p, int pn, int t, int tid,
    const float* __restrict__ bih2, const float* __restrict__ bhh2)
{
    const int b0sel = bid >> 5;
    const int n = bid & 31;
    const int w = tid >> 5, lane = tid & 31;
    const int g = lane >> 2, tig = lane & 3;
    const int b_glob = b0sel*64 + w*8 + g;

    const uint4* wpn = (const uint4*)g_W2h + (size_t)n*40*32 + lane;
    const __half* h1p = g_h1h + (size_t)b_glob*H1S + tig*2;
    const __half* h2p = g_h2h[p] + (size_t)b_glob*KEY + tig*2;

    float cA[4] = {0.f, 0.f, 0.f, 0.f};
    float cB[4] = {0.f, 0.f, 0.f, 0.f};
    #pragma unroll 4
    for (int kc = 0; kc < 32; kc += 2) {
        uint4 a = wpn[(size_t)kc*32];
        const unsigned* xp = (const unsigned*)(h1p + kc*16);
        mma16816(cA, a.x, a.y, a.z, a.w, xp[0], xp[4]);
        uint4 a2 = wpn[(size_t)(kc+1)*32];
        const unsigned* xp2 = (const unsigned*)(h1p + (kc+1)*16);
        mma16816(cB, a2.x, a2.y, a2.z, a2.w, xp2[0], xp2[4]);
    }
    #pragma unroll
    for (int kc = 32; kc < 40; kc += 2) {
        uint4 a = wpn[(size_t)kc*32];
        const unsigned* xp = (const unsigned*)(h2p + (kc-32)*16);
        mma16816(cA, a.x, a.y, a.z, a.w, xp[0], xp[4]);
        uint4 a2 = wpn[(size_t)(kc+1)*32];
        const unsigned* xp2 = (const unsigned*)(h2p + (kc-31)*16);
        mma16816(cB, a2.x, a2.y, a2.z, a2.w, xp2[0], xp2[4]);
    }
    float v0 = cA[0]+cB[0], v1 = cA[1]+cB[1];
    float v2 = cA[2]+cB[2], v3 = cA[3]+cB[3];
    float u0 = __shfl_xor_sync(~0u, v0, 16);
    float u1 = __shfl_xor_sync(~0u, v1, 16);
    float u2 = __shfl_xor_sync(~0u, v2, 16);
    float u3 = __shfl_xor_sync(~0u, v3, 16);
    if (g < 4) {
        int j = n*4 + g;
        int rl = w*8 + tig*2;
        float bi = bih2[j]         + bhh2[j];
        float bf = bih2[j +   KEY] + bhh2[j +   KEY];
        float bg = bih2[j + 2*KEY] + bhh2[j + 2*KEY];
        float bo = bih2[j + 3*KEY] + bhh2[j + 3*KEY];
        int b = b0sel*64 + rl;
        #pragma unroll
        for (int rr = 0; rr < 2; rr++) {
            float gi = (rr ? v1 : v0) + bi, gf = (rr ? u1 : u0) + bf;
            float gg = (rr ? v3 : v2) + bg, go = (rr ? u3 : u2) + bo;
            int bb = b + rr;
            int idx = j*BB + bb;
            float c = sigf(gf)*g_c2T[idx] + sigf(gi)*tanhf(gg);
            g_c2T[idx] = c;
            float h = sigf(go)*tanhf(c);
            g_h2T[pn][idx] = h;
            g_h2h[pn][(size_t)bb*KEY + j] = __float2half_rn(h);
            g_h2ctxT[(size_t)j*NROWS + t*BB + bb] = h;
        }
    }
}

// =============================================================================
// Persistent decoder kernel
// =============================================================================
__global__ __launch_bounds__(NTHR, 2) void decoder_kernel(
    const float* __restrict__ keys, const float* __restrict__ values,
    const int* __restrict__ lens, const int* __restrict__ text,
    const float* __restrict__ emb_table,
    const float* __restrict__ Wih1, const float* __restrict__ Whh1,
    const float* __restrict__ bih1, const float* __restrict__ bhh1,
    const float* __restrict__ Wih2, const float* __restrict__ Whh2,
    const float* __restrict__ bih2, const float* __restrict__ bhh2)
{
    __shared__ float sm[4160];
    const int tid = threadIdx.x;
    const int bid = blockIdx.x;
    const int gid = bid * NTHR + tid;
    const int gstride = NBLK * NTHR;   // 75776
    unsigned nb = 0, nbB = 0;

    // ---------------- pre-stage ----------------
    for (int i = gid; i < H1S*BB; i += gstride) {
        g_c1T[i] = 0.f; g_h1h[i] = __float2half_rn(0.f);
    }
    for (int i = gid; i < 2*KEY*BB; i += gstride) {
        ((float*)g_h2T)[i] = 0.f;
        ((__half*)g_h2h)[i] = __float2half_rn(0.f);
    }
    for (int i = gid; i < KEY*BB; i += gstride) g_c2T[i] = 0.f;
    for (int i = gid; i < VAL*BB; i += gstride) g_ctxh[i] = __float2half_rn(0.f);

    // embedding gather -> fp16 [t][b][h]
    for (int i = gid; i < T_DEC*BB*HID; i += gstride) {
        int h = i & (HID-1);
        int r = i >> 8;            // t*BB + b
        int b = r & (BB-1);
        int t = r >> 7;
        g_embh[i] = __float2half_rn(emb_table[text[b*T_DEC + t]*HID + h]);
    }

    // pack W1 (emb|h1) mma A-fragments: [n 128][kc 48][lane 32][8 halves]
    for (int i = gid; i < 128*NKC*32*8; i += gstride) {
        int idx  = i & 7;
        int lane = (i >> 3) & 31;
        int kc   = (i >> 8) % NKC;
        int n    = i / (NKC*256);
        int g_   = lane >> 2, tig = lane & 3;
        int r_   = idx >> 1, h_ = idx & 1;
        int m    = g_ + ((r_ & 1) ? 8 : 0);
        int kadd = (r_ >= 2) ? 8 : 0;
        int k_local = kc*16 + tig*2 + h_ + kadd;      // 0..767 (emb|h1)
        int c = n*4 + (m & 3) + H1S * (m >> 2);
        int k_global = (k_local < HID) ? k_local : k_local + VAL; // skip ctx
        float v = (k_global < HID+VAL) ? Wih1[c*(HID+VAL) + k_global]
                                       : Whh1[c*H1S + (k_global - HID - VAL)];
        g_W1h[i] = __float2half_rn(v);
    }
    // pack W1 ctx-part fragments: [n 128][kc 8][lane 32][8 halves]
    for (int i = gid; i < 128*8*32*8; i += gstride) {
        int idx  = i & 7;
        int lane = (i >> 3) & 31;
        int kc   = (i >> 8) & 7;
        int n    = i / (8*256);
        int g_   = lane >> 2, tig = lane & 3;
        int r_   = idx >> 1, h_ = idx & 1;
        int m    = g_ + ((r_ & 1) ? 8 : 0);
        int kadd = (r_ >= 2) ? 8 : 0;
        int k_local = kc*16 + tig*2 + h_ + kadd;      // 0..127 (ctx)
        int c = n*4 + (m & 3) + H1S * (m >> 2);
        g_W1ch[i] = __float2half_rn(Wih1[c*(HID+VAL) + HID + k_local]);
    }
    // pack W2 fragments: [n 32][kc 40][lane 32][8 halves], K = h1(512)|h2(128)
    for (int i = gid; i < 32*40*32*8; i += gstride) {
        int idx  = i & 7;
        int lane = (i >> 3) & 31;
        int kc   = (i >> 8) % 40;
        int n    = i / (40*256);
        int g_   = lane >> 2, tig = lane & 3;
        int r_   = idx >> 1, h_ = idx & 1;
        int m    = g_ + ((r_ & 1) ? 8 : 0);
        int kadd = (r_ >= 2) ? 8 : 0;
        int k_local = kc*16 + tig*2 + h_ + kadd;      // 0..639
        int c = n*4 + (m & 3) + KEY * (m >> 2);
        float v = (k_local < H1S) ? Wih2[c*H1S + k_local]
                                  : Whh2[c*KEY + (k_local - H1S)];
        g_W2h[i] = __float2half_rn(v);
    }

    // convert V to fp16 ([t][b][v] layout kept)
    {
        const int n4 = (T_ENC*BB*VAL) / 4;
        const float4* v4 = (const float4*)values;
        __half2* vh2 = (__half2*)g_vh;
        for (int i = gid; i < n4; i += gstride) {
            float4 f = v4[i];
            vh2[2*i]   = __floats2half2_rn(f.x, f.y);
            vh2[2*i+1] = __floats2half2_rn(f.z, f.w);
        }
    }

    // transpose K -> fp16 [b][k][t] via smem tiles (64 t x 32 k per job)
    for (int j = bid; j < 128*4*32; j += NBLK) {
        int b  = j >> 7;
        int kt = (j >> 5) & 3;
        int tt = j & 31;
        float* st = sm;           // [64][33]
        #pragma unroll
        for (int p8 = 0; p8 < 8; p8++) {
            int trow = p8*8 + (tid >> 5);
            int kcol = tid & 31;
            st[trow*33 + kcol] =
                keys[((size_t)(tt*64 + trow)*BB + b)*KEY + kt*32 + kcol];
        }
        __syncthreads();
        #pragma unroll
        for (int p4 = 0; p4 < 8; p4++) {
            int kr   = p4*4 + (tid >> 6);
            int tcol = tid & 63;
            g_khT[((size_t)b*KEY + kt*32 + kr)*T_ENC + tt*64 + tcol] =
                __float2half_rn(st[tcol*33 + kr]);
        }
        __syncthreads();
    }
    nb++; gbar(bid, nb);

    // ---------------- A'_0: partial gates for t=0 (h1h = 0) ----------------
    if (bid < 256) aprime_job(bid, 0, tid);
    nb++; gbar(bid, nb);

    // ================= decode loop =================
    for (int t = 0; t < T_DEC; t++) {
        const int p = t & 1, pn = p ^ 1;

        // ---------- Interval 1: A'' HMMA + cell1 ----------
        if (bid < 256) aseg_job(bid, tid, bih1, bhh1);
        nb++; gbar(bid, nb);

        // ---------- Interval 2 ----------
        // blocks 0-63: B-HMMA+cell2; 64-239: A' x1; 240-255: idle;
        // 256-295: A' x2 (off the C path)
        if (bid < 64) {
            bstage_job(bid, p, pn, t, tid, bih2, bhh2);
        } else if (bid < 240) {
            if (t + 1 < T_DEC) aprime_job(bid - 64, t + 1, tid);
        } else if (bid >= 256) {
            if (t + 1 < T_DEC) {
                aprime_job(176 + (bid - 256), t + 1, tid);
                aprime_job(216 + (bid - 256), t + 1, tid);
            }
        }

        if (bid < 256) {
            nbB++; bar256(bid, nbB);

            // ----- Attention (2-way split): b = bid&127, chunk = bid>>7 -----
            const int b = bid & 127;
            const int chunk = bid >> 7;
            const int lane = tid & 31, w = tid >> 5;
            const int len = lens[b];
            const int c0 = chunk << 10;
            int lenc = len - c0; if (lenc > 1024) lenc = 1024;

            float* s_p  = sm;           // [1024]
            float* s_pt = sm + 1024;    // [8][128]
            float* s_h2 = sm + 2048;    // [128]
            float* s_r  = sm + 2176;    // [16]
            float* s_c  = sm + 2200;    // combine scratch
            if (tid < 128) s_h2[tid] = g_h2T[pn][tid*BB + b];
            __syncthreads();

            // --- E pass ---
            const int t0 = tid * 4;
            float ef[4] = {0.f, 0.f, 0.f, 0.f};
            if (lenc > 0) {
                const __half* kp = g_khT + (size_t)b*KEY*T_ENC + c0 + t0;
                #pragma unroll 2
                for (int k = 0; k < KEY; k += 4) {
                    uint2 u0 = *(const uint2*)(kp + (size_t)k*T_ENC);
                    uint2 u1 = *(const uint2*)(kp + (size_t)(k+1)*T_ENC);
                    uint2 u2 = *(const uint2*)(kp + (size_t)(k+2)*T_ENC);
                    uint2 u3 = *(const uint2*)(kp + (size_t)(k+3)*T_ENC);
                    float h0 = s_h2[k], h1 = s_h2[k+1];
                    float h2v = s_h2[k+2], h3 = s_h2[k+3];
                    float2 a, bb;
                    a = __half22float2(((__half2*)&u0)[0]);
                    bb = __half22float2(((__half2*)&u0)[1]);
                    ef[0] += h0*a.x; ef[1] += h0*a.y; ef[2] += h0*bb.x; ef[3] += h0*bb.y;
                    a = __half22float2(((__half2*)&u1)[0]);
                    bb = __half22float2(((__half2*)&u1)[1]);
                    ef[0] += h1*a.x; ef[1] += h1*a.y; ef[2] += h1*bb.x; ef[3] += h1*bb.y;
                    a = __half22float2(((__half2*)&u2)[0]);
                    bb = __half22float2(((__half2*)&u2)[1]);
                    ef[0] += h2v*a.x; ef[1] += h2v*a.y; ef[2] += h2v*bb.x; ef[3] += h2v*bb.y;
                    a = __half22float2(((__half2*)&u3)[0]);
                    bb = __half22float2(((__half2*)&u3)[1]);
                    ef[0] += h3*a.x; ef[1] += h3*a.y; ef[2] += h3*bb.x; ef[3] += h3*bb.y;
                }
            }
            float e[4];
            #pragma unroll
            for (int i = 0; i < 4; i++)
                e[i] = (t0 + i < lenc) ? ef[i] : -3.0e38f;

            float tm = fmaxf(fmaxf(e[0], e[1]), fmaxf(e[2], e[3]));
            #pragma unroll
            for (int off = 16; off; off >>= 1)
                tm = fmaxf(tm, __shfl_xor_sync(~0u, tm, off));
            if (lane == 0) s_r[w] = tm;
            __syncthreads();
            float M = s_r[0];
            #pragma unroll
            for (int ww = 1; ww < 8; ww++) M = fmaxf(M, s_r[ww]);

            float pv[4];
            float lsum = 0.f;
            #pragma unroll
            for (int i = 0; i < 4; i++) {
                pv[i] = expf(e[i] - M);
                lsum += pv[i];
            }
            *(float4*)&s_p[t0] = make_float4(pv[0], pv[1], pv[2], pv[3]);
            #pragma unroll
            for (int off = 16; off; off >>= 1)
                lsum += __shfl_xor_sync(~0u, lsum, off);
            if (lane == 0) s_r[8 + w] = lsum;
            __syncthreads();
            float L = 0.f;
            #pragma unroll
            for (int ww = 0; ww < 8; ww++) L += s_r[8 + ww];

            // --- V pass: chunk-4 double-buffered pipeline ---
            const int vq = (tid & 31) * 4;
            const int tg = tid >> 5;
            float a0 = 0.f, a1 = 0.f, a2 = 0.f, a3 = 0.f;
            if (lenc > 0) {
                const int itmax = (lenc + 7) >> 3;
                const int nc = (itmax + 3) >> 2;
                uint2 bufA[4], bufB[4];
                const __half* vbase = g_vh + ((size_t)c0*BB + b)*VAL + vq;

#define V_LOAD(BUF, CH) do { \
                int itb_ = (CH)*4; \
                _Pragma("unroll") \
                for (int i_ = 0; i_ < 4; i_++) { \
                    int tl_ = (itb_ + i_)*8 + tg; \
                    (BUF)[i_] = *(const uint2*)(vbase + (size_t)tl_*BB*VAL); \
                } } while (0)

#define V_COMP(BUF, CH) do { \
                int itb_ = (CH)*4; \
                _Pragma("unroll") \
                for (int i_ = 0; i_ < 4; i_++) { \
                    int tl_ = (itb_ + i_)*8 + tg; \
                    float pw_ = s_p[tl_]; \
                    float2 f01_ = __half22float2(((__half2*)&(BUF)[i_])[0]); \
                    float2 f23_ = __half22float2(((__half2*)&(BUF)[i_])[1]); \
                    a0 += pw_*f01_.x; a1 += pw_*f01_.y; \
                    a2 += pw_*f23_.x; a3 += pw_*f23_.y; \
                } } while (0)

                V_LOAD(bufA, 0);
                if (nc > 1) V_LOAD(bufB, 1);
                for (int ch = 0; ch < nc; ch += 2) {
                    V_COMP(bufA, ch);
                    if (ch + 2 < nc) V_LOAD(bufA, ch + 2);
                    if (ch + 1 < nc) {
                        V_COMP(bufB, ch + 1);
                        if (ch + 3 < nc) V_LOAD(bufB, ch + 3);
                    }
                }
            }
            *(float4*)&s_pt[tg*128 + vq] = make_float4(a0, a1, a2, a3);
            __syncthreads();
            // write partial (unnormalized acc + m + l)
            float* ap = (float*)&g_att[chunk][b][0];
            if (tid < 128) {
                float s = 0.f;
                #pragma unroll
                for (int g8 = 0; g8 < 8; g8++) s += s_pt[g8*128 + tid];
                ap[tid] = s;
            }
            if (tid == 0) { ap[128] = M; ap[129] = L; }
            __threadfence();
            __syncthreads();
            if (tid == 0) *(unsigned*)s_c = atomicAdd(&g_cflag[b], 1u);
            __syncthreads();
            if (*(unsigned*)s_c == 2u*(unsigned)t + 1u) {
                // second block to arrive combines (deterministic math)
                __threadfence();
                float m0 = g_att[0][b][128], l0 = g_att[0][b][129];
                float m1 = g_att[1][b][128], l1 = g_att[1][b][129];
                float Mf = fmaxf(m0, m1);
                float w0 = expf(m0 - Mf), w1 = expf(m1 - Mf);
                float Linv = 1.f / (l0*w0 + l1*w1);
                if (tid < 128) {
                    float cx = (g_att[0][b][tid]*w0 + g_att[1][b][tid]*w1) * Linv;
                    g_ctxh[b*VAL + tid] = __float2half_rn(cx);
                    g_h2ctxT[(size_t)(KEY + tid)*NROWS + t*BB + b] = cx;
                }
            }
        }
        nb++; gbar(bid, nb);
    }
}

// ---------------- final logits GEMM -------------
__global__ __launch_bounds__(256) void pred_kernel(
    const float* __restrict__ Wlin, const float* __restrict__ blin,
    float* __restrict__ out)
{
    __shared__ float As[16][68];
    __shared__ float Bs[16][68];
    const int r0 = blockIdx.x * 64;
    const int v0 = blockIdx.y * 64;
    const int tid = threadIdx.x;
    const int m0 = (tid & 15) * 4;
    const int n0 = (tid >> 4) * 4;
    float acc[4][4] = {};

    for (int k0 = 0; k0 < 256; k0 += 16) {
        #pragma unroll
        for (int i = 0; i < 4; i++) {
            int li = i*256 + tid;
            int kk = li >> 6, m = li & 63;
            As[kk][m] = g_h2ctxT[(size_t)(k0 + kk)*NROWS + r0 + m];
        }
        #pragma unroll
        for (int i = 0; i < 4; i++) {
            int li = i*256 + tid;
            int n = li >> 4, kk = li & 15;
            int v = v0 + n;
            Bs[kk][n] = (v < VOCAB) ? Wlin[v*256 + k0 + kk] : 0.f;
        }
        __syncthreads();
        #pragma unroll
        for (int kk = 0; kk < 16; kk++) {
            float4 a = *(const float4*)&As[kk][m0];
            float4 bq = *(const float4*)&Bs[kk][n0];
            float av[4] = {a.x, a.y, a.z, a.w};
            float bv[4] = {bq.x, bq.y, bq.z, bq.w};
            #pragma unroll
            for (int i = 0; i < 4; i++)
                #pragma unroll
                for (int j = 0; j < 4; j++)
                    acc[i][j] += av[i] * bv[j];
        }
        __syncthreads();
    }
    #pragma unroll
    for (int i = 0; i < 4; i++) {
        int r = r0 + m0 + i;
        int b = r & 127, t = r >> 7;
        #pragma unroll
        for (int j = 0; j < 4; j++) {
            int v = v0 + n0 + j;
            if (v < VOCAB)
                out[((size_t)b*T_DEC + t)*VOCAB + v] = acc[i][j] + blin[v];
        }
    }
}

// ---------------- launch (decoder FIRST so ncu -s 5 lands on it) ---------
extern "C" void kernel_launch(void* const* d_in, const int* in_sizes, int n_in,
                              void* d_out, int out_size)
{
    const float* keys      = (const float*)d_in[0];
    const float* values    = (const float*)d_in[1];
    const int*   lens      = (const int*)  d_in[2];
    const int*   text      = (const int*)  d_in[3];
    const float* emb_table = (const float*)d_in[4];
    const float* Wih1      = (const float*)d_in[5];
    const float* Whh1      = (const float*)d_in[6];
    const float* bih1      = (const float*)d_in[7];
    const float* bhh1      = (const float*)d_in[8];
    const float* Wih2      = (const float*)d_in[9];
    const float* Whh2      = (const float*)d_in[10];
    const float* bih2      = (const float*)d_in[11];
    const float* bhh2      = (const float*)d_in[12];
    const float* Wlin      = (const float*)d_in[13];
    const float* blin      = (const float*)d_in[14];
    float* out = (float*)d_out;

    // Barrier/flag counters are statically zero-initialized; reset_bar_kernel
    // at the END of each launch restores that invariant for the next replay.
    decoder_kernel<<<NBLK, NTHR>>>(keys, values, lens, text, emb_table,
                                   Wih1, Whh1, bih1, bhh1,
                                   Wih2, Whh2, bih2, bhh2);
    pred_kernel<<<dim3(NROWS/64, (VOCAB + 63)/64), 256>>>(Wlin, blin, out);
    reset_bar_kernel<<<1, 512>>>();
}